// round 10
// baseline (speedup 1.0000x reference)
#include <cuda_runtime.h>
#include <cstdint>

#define NB   4
#define TQ   2048
#define NE   1024
#define HD   128
#define TKF  4096
#define NM   16384

typedef unsigned long long ull;

// ---------------- packed f32x2 helpers (sm_103a only) ----------------
__device__ __forceinline__ ull dup2(float x) {
    ull r; asm("mov.b64 %0, {%1, %1};" : "=l"(r) : "f"(x)); return r;
}
__device__ __forceinline__ float2 u2f(ull v) {
    float2 r; asm("mov.b64 {%0, %1}, %2;" : "=f"(r.x), "=f"(r.y) : "l"(v)); return r;
}
__device__ __forceinline__ ull ffma2(ull a, ull b, ull c) {
    ull d; asm("fma.rn.f32x2 %0, %1, %2, %3;" : "=l"(d) : "l"(a), "l"(b), "l"(c)); return d;
}
__device__ __forceinline__ ull fmul2(ull a, ull b) {
    ull d; asm("mul.rn.f32x2 %0, %1, %2;" : "=l"(d) : "l"(a), "l"(b)); return d;
}

// ---------------- cp.async helpers ----------------
__device__ __forceinline__ void cp16(uint32_t dst_smem, const void* src) {
    asm volatile("cp.async.ca.shared.global [%0], [%1], 16;"
                 :: "r"(dst_smem), "l"(src));
}
__device__ __forceinline__ void cp_commit() {
    asm volatile("cp.async.commit_group;");
}
__device__ __forceinline__ void cp_wait0() {
    asm volatile("cp.async.wait_group 0;");
}

// ---------------- device scratch ----------------
__device__ float g_q [(size_t)NB * TQ  * HD];
__device__ float g_kf[(size_t)NB * TKF * HD];
__device__ float g_vf[(size_t)NB * TKF * HD];
// top-k scratch: per query, 2 halves x top-32 (val, idx)
__device__ float g_mv[(size_t)NB * TQ * 64];
__device__ int   g_mi[(size_t)NB * TQ * 64];

// =========================================================================
// 1) prefix copy
// =========================================================================
__global__ __launch_bounds__(256) void copy_prefix_kernel(
    const float* __restrict__ ki, const float* __restrict__ vi,
    const int* __restrict__ idxp)
{
    const int s  = idxp[0] * HD;
    const int e4 = blockIdx.x * 256 + threadIdx.x;
    const int d4 = e4 & 31;
    const int t  = (e4 >> 5) & (TQ - 1);
    const int b  = e4 >> 16;
    const size_t src = ((size_t)b * TQ + t) * NE + s + (size_t)d4 * 4;
    const size_t dst = ((size_t)b * TKF + t) * HD + (size_t)d4 * 4;
    *(float4*)(g_kf + dst) = *(const float4*)(ki + src);
    *(float4*)(g_vf + dst) = *(const float4*)(vi + src);
}

// =========================================================================
// 2) fused projection GEMM (packed FFMA2) — unchanged
// =========================================================================
__global__ __launch_bounds__(256) void proj_kernel(
    const float* __restrict__ X,
    const float* __restrict__ Wq, const float* __restrict__ Wk,
    const float* __restrict__ Wv,
    const float* __restrict__ bq, const float* __restrict__ bk,
    const float* __restrict__ bv)
{
    __shared__ float As[64][17];
    __shared__ float Bs[16][128];
    const int mode = blockIdx.y;
    const float* W    = (mode == 0) ? Wq : (mode == 1) ? Wk : Wv;
    const float* bias = (mode == 0) ? bq : (mode == 1) ? bk : bv;
    float* dst        = (mode == 0) ? g_q : (mode == 1) ? g_kf : g_vf;

    const int t   = threadIdx.x;
    const int bm0 = blockIdx.x * 64;
    const int tr  = t >> 4;
    const int tc  = t & 15;

    ull acc[4][4];
    #pragma unroll
    for (int i = 0; i < 4; i++)
        #pragma unroll
        for (int j = 0; j < 4; j++) acc[i][j] = 0ULL;

    const int ar = t >> 2, ac = (t & 3) * 4;
    const int br = t >> 5, bc = (t & 31) * 4;

    for (int k0 = 0; k0 < NE; k0 += 16) {
        float4 av = *(const float4*)(X + (size_t)(bm0 + ar) * NE + k0 + ac);
        As[ar][ac + 0] = av.x; As[ar][ac + 1] = av.y;
        As[ar][ac + 2] = av.z; As[ar][ac + 3] = av.w;
        *(float4*)(&Bs[br][bc])     = *(const float4*)(W + (size_t)(k0 + br) * HD + bc);
        *(float4*)(&Bs[br + 8][bc]) = *(const float4*)(W + (size_t)(k0 + br + 8) * HD + bc);
        __syncthreads();
        #pragma unroll
        for (int kk = 0; kk < 16; kk++) {
            ull pa[4];
            #pragma unroll
            for (int i = 0; i < 4; i++) pa[i] = dup2(As[tr * 4 + i][kk]);
            ulonglong2 b01 = *(const ulonglong2*)(&Bs[kk][tc * 8]);
            ulonglong2 b23 = *(const ulonglong2*)(&Bs[kk][tc * 8 + 4]);
            #pragma unroll
            for (int i = 0; i < 4; i++) {
                acc[i][0] = ffma2(pa[i], b01.x, acc[i][0]);
                acc[i][1] = ffma2(pa[i], b01.y, acc[i][1]);
                acc[i][2] = ffma2(pa[i], b23.x, acc[i][2]);
                acc[i][3] = ffma2(pa[i], b23.y, acc[i][3]);
            }
        }
        __syncthreads();
    }

    float4 bb0 = *(const float4*)(bias + tc * 8);
    float4 bb1 = *(const float4*)(bias + tc * 8 + 4);
    #pragma unroll
    for (int i = 0; i < 4; i++) {
        int row = bm0 + tr * 4 + i;
        int bi  = row >> 11;
        int tt  = row & (TQ - 1);
        size_t orow = (mode == 0) ? (size_t)row : ((size_t)bi * TKF + TQ + tt);
        float2 a0 = u2f(acc[i][0]), a1 = u2f(acc[i][1]);
        float2 a2 = u2f(acc[i][2]), a3 = u2f(acc[i][3]);
        float4 o0 = make_float4(a0.x + bb0.x, a0.y + bb0.y, a1.x + bb0.z, a1.y + bb0.w);
        float4 o1 = make_float4(a2.x + bb1.x, a2.y + bb1.y, a3.x + bb1.z, a3.y + bb1.w);
        *(float4*)(dst + orow * HD + tc * 8)     = o0;
        *(float4*)(dst + orow * HD + tc * 8 + 4) = o1;
    }
}

// =========================================================================
// 3) causal flash attention — double-buffered cp.async (unchanged)
// =========================================================================
#define ATTN_SMEM (32768 + 65536 + 65536 + 64 * 68 * 4)

__global__ __launch_bounds__(256) void attn_kernel(
    const float* __restrict__ gate, float* __restrict__ out)
{
    extern __shared__ float smem_dyn[];
    float4* Qs  = (float4*)smem_dyn;
    float4* Ks0 = Qs + 64 * 32;
    float4* Ks1 = Ks0 + 64 * 32;
    float4* Vs0 = Ks1 + 64 * 32;
    float4* Vs1 = Vs0 + 64 * 32;
    float*  Ss  = (float*)(Vs1 + 64 * 32);

    const int t  = threadIdx.x;
    const int b  = blockIdx.y;
    const int qb = blockIdx.x;
    const int tq = t >> 4;
    const int tk = t & 15;
    const float scale = 0.08838834764831845f;

    const float4* qsrc = (const float4*)(g_q + ((size_t)(b * TQ + qb * 64)) * HD);
    #pragma unroll
    for (int i = 0; i < 8; i++) {
        int idx = t + i * 256; int r = idx >> 5, c = idx & 31;
        Qs[r * 32 + (c ^ ((r >> 2) & 7))] = qsrc[idx];
    }

    float m[4], l[4];
    ull ac2[4][4];
    #pragma unroll
    for (int i = 0; i < 4; i++) {
        m[i] = -1e30f; l[i] = 0.f;
        #pragma unroll
        for (int j = 0; j < 4; j++) ac2[i][j] = 0ULL;
    }

    const float4* kbase = (const float4*)(g_kf + ((size_t)b * TKF) * HD);
    const float4* vbase = (const float4*)(g_vf + ((size_t)b * TKF) * HD);
    const int ntiles = qb + 33;

    {
        uint32_t kd = (uint32_t)__cvta_generic_to_shared(Ks0);
        uint32_t vd = (uint32_t)__cvta_generic_to_shared(Vs0);
        #pragma unroll
        for (int i = 0; i < 8; i++) {
            int idx = t + i * 256; int r = idx >> 5, c = idx & 31;
            uint32_t off = (uint32_t)(r * 32 + (c ^ ((r >> 2) & 7))) * 16u;
            cp16(kd + off, kbase + idx);
            cp16(vd + off, vbase + idx);
        }
        cp_commit();
    }

    for (int tile = 0; tile < ntiles; tile++) {
        cp_wait0();
        __syncthreads();
        const float4* Ks = (tile & 1) ? Ks1 : Ks0;
        const float4* Vs = (tile & 1) ? Vs1 : Vs0;

        if (tile + 1 < ntiles) {
            float4* Kn = (tile & 1) ? Ks0 : Ks1;
            float4* Vn = (tile & 1) ? Vs0 : Vs1;
            uint32_t kd = (uint32_t)__cvta_generic_to_shared(Kn);
            uint32_t vd = (uint32_t)__cvta_generic_to_shared(Vn);
            const float4* ks = kbase + (size_t)(tile + 1) * 64 * 32;
            const float4* vs = vbase + (size_t)(tile + 1) * 64 * 32;
            #pragma unroll
            for (int i = 0; i < 8; i++) {
                int idx = t + i * 256; int r = idx >> 5, c = idx & 31;
                uint32_t off = (uint32_t)(r * 32 + (c ^ ((r >> 2) & 7))) * 16u;
                cp16(kd + off, ks + idx);
                cp16(vd + off, vs + idx);
            }
            cp_commit();
        }

        ull s2[4][4];
        #pragma unroll
        for (int i = 0; i < 4; i++)
            #pragma unroll
            for (int j = 0; j < 4; j++) s2[i][j] = 0ULL;

        #pragma unroll 4
        for (int c = 0; c < 32; c++) {
            ulonglong2 a2[4], k2[4];
            #pragma unroll
            for (int i = 0; i < 4; i++)
                a2[i] = *(const ulonglong2*)&Qs[(4 * tq + i) * 32 + (c ^ (tq & 7))];
            #pragma unroll
            for (int j = 0; j < 4; j++)
                k2[j] = *(const ulonglong2*)&Ks[(4 * tk + j) * 32 + (c ^ (tk & 7))];
            #pragma unroll
            for (int i = 0; i < 4; i++)
                #pragma unroll
                for (int j = 0; j < 4; j++)
                    s2[i][j] = ffma2(a2[i].x, k2[j].x,
                               ffma2(a2[i].y, k2[j].y, s2[i][j]));
        }

        float s[4][4];
        const bool lastTile = (tile == ntiles - 1);
        #pragma unroll
        for (int i = 0; i < 4; i++)
            #pragma unroll
            for (int j = 0; j < 4; j++) {
                float2 p = u2f(s2[i][j]);
                s[i][j] = (p.x + p.y) * scale;
                if (lastTile && (4 * tk + j > 4 * tq + i)) s[i][j] = -1e30f;
            }

        float tmax[4];
        #pragma unroll
        for (int i = 0; i < 4; i++)
            tmax[i] = fmaxf(fmaxf(s[i][0], s[i][1]), fmaxf(s[i][2], s[i][3]));
        #pragma unroll
        for (int o = 1; o < 16; o <<= 1)
            #pragma unroll
            for (int i = 0; i < 4; i++)
                tmax[i] = fmaxf(tmax[i], __shfl_xor_sync(0xffffffffu, tmax[i], o));

        float corr[4], rs[4];
        #pragma unroll
        for (int i = 0; i < 4; i++) {
            float mn = fmaxf(m[i], tmax[i]);
            corr[i] = __expf(m[i] - mn);
            m[i] = mn;
            rs[i] = 0.f;
            #pragma unroll
            for (int j = 0; j < 4; j++) {
                s[i][j] = __expf(s[i][j] - mn);
                rs[i] += s[i][j];
            }
        }
        #pragma unroll
        for (int o = 1; o < 16; o <<= 1)
            #pragma unroll
            for (int i = 0; i < 4; i++)
                rs[i] += __shfl_xor_sync(0xffffffffu, rs[i], o);
        #pragma unroll
        for (int i = 0; i < 4; i++) {
            l[i] = l[i] * corr[i] + rs[i];
            ull c2 = dup2(corr[i]);
            #pragma unroll
            for (int j = 0; j < 4; j++) ac2[i][j] = fmul2(ac2[i][j], c2);
            *(float4*)&Ss[(4 * tq + i) * 68 + 4 * tk] =
                make_float4(s[i][0], s[i][1], s[i][2], s[i][3]);
        }
        __syncthreads();

        #pragma unroll 2
        for (int jj = 0; jj < 16; jj++) {
            float4 p[4];
            #pragma unroll
            for (int i = 0; i < 4; i++)
                p[i] = *(const float4*)&Ss[(4 * tq + i) * 68 + jj * 4];
            #pragma unroll
            for (int e = 0; e < 4; e++) {
                int j = jj * 4 + e;
                int key = (j >> 2) & 7;
                ulonglong2 v0 = *(const ulonglong2*)&Vs[j * 32 + (tk ^ key)];
                ulonglong2 v1 = *(const ulonglong2*)&Vs[j * 32 + ((16 + tk) ^ key)];
                #pragma unroll
                for (int i = 0; i < 4; i++) {
                    float pv = (e == 0) ? p[i].x : (e == 1) ? p[i].y
                             : (e == 2) ? p[i].z : p[i].w;
                    ull pv2 = dup2(pv);
                    ac2[i][0] = ffma2(pv2, v0.x, ac2[i][0]);
                    ac2[i][1] = ffma2(pv2, v0.y, ac2[i][1]);
                    ac2[i][2] = ffma2(pv2, v1.x, ac2[i][2]);
                    ac2[i][3] = ffma2(pv2, v1.y, ac2[i][3]);
                }
            }
        }
        __syncthreads();
    }

    const float gv = gate[0];
    #pragma unroll
    for (int i = 0; i < 4; i++) {
        float inv = gv / l[i];
        size_t row = (size_t)(b * TQ + qb * 64 + 4 * tq + i) * HD;
        float2 a0 = u2f(ac2[i][0]), a1 = u2f(ac2[i][1]);
        float2 a2 = u2f(ac2[i][2]), a3 = u2f(ac2[i][3]);
        float4 o0 = make_float4(a0.x * inv, a0.y * inv, a1.x * inv, a1.y * inv);
        float4 o1 = make_float4(a2.x * inv, a2.y * inv, a3.x * inv, a3.y * inv);
        *(float4*)(out + row + 4 * tk)      = o0;
        *(float4*)(out + row + 64 + 4 * tk) = o1;
    }
}

// =========================================================================
// 4a) kNN score kernel: split-K (z halves), exact per-half top-32 lists.
//     Score chains + selection identical to R9; gather removed.
// =========================================================================
#define MEMS_SMEM 49152

__global__ __launch_bounds__(128, 3) void mem_score_kernel(
    const float* __restrict__ mem_keys)
{
    extern __shared__ float msm[];
    float4* Qs   = (float4*)msm;                  // [0, 16KB)
    float4* Ks   = (float4*)(msm + 4096);         // [16KB, 48KB)
    float*  lv_s = msm;                           // overlay [0, 16KB)
    int*    li_s = (int*)(msm + 4096);            // overlay [16KB, 32KB)

    const int t    = threadIdx.x;                 // 0..127
    const int b    = blockIdx.y;
    const int q0   = blockIdx.x * 32;
    const int z    = blockIdx.z;                  // key half
    const int pair = t >> 3;                      // queries (pair, pair+16)
    const int g    = t & 7;
    const int h    = g >> 2;
    const int lane = t & 31;
    const int zbase = z * (NM / 2);

    const float4* qsrc = (const float4*)(g_q + ((size_t)(b * TQ + q0)) * HD);
    #pragma unroll
    for (int i = 0; i < 8; i++) {
        int idx = t + i * 128; int r = idx >> 5, c = idx & 31;
        Qs[r * 32 + (c ^ (r & 7))] = qsrc[idx];
    }

    float lv[32]; int li[32];
    #pragma unroll
    for (int i = 0; i < 32; i++) { lv[i] = -1e30f; li[i] = 0; }
    float Tsh = -1e30f;

    const float4* kb = (const float4*)(mem_keys + ((size_t)b * NM + zbase) * HD);

    for (int tile = 0; tile < (NM / 2) / 64; tile++) {
        // synchronous cp.async tile load (occupancy hides latency)
        {
            uint32_t kd = (uint32_t)__cvta_generic_to_shared(Ks);
            const float4* ks = kb + (size_t)tile * 2048;
            #pragma unroll
            for (int i = 0; i < 16; i++) {
                int idx = t + i * 128; int r = idx >> 5, c = idx & 31;
                uint32_t off = (uint32_t)(r * 32 + (c ^ ((r >> 3) & 7))) * 16u;
                cp16(kd + off, ks + idx);
            }
            cp_commit(); cp_wait0();
        }
        __syncthreads();

        // ---- scores (chains bit-identical to R9) ----
        float sA[8], sB[8];
        #pragma unroll
        for (int j = 0; j < 8; j++) { sA[j] = 0.f; sB[j] = 0.f; }
        #pragma unroll 4
        for (int c = 0; c < 32; c++) {
            float4 aA = Qs[pair * 32 + (c ^ (pair & 7))];
            float4 aB = Qs[(pair + 16) * 32 + (c ^ (pair & 7))];
            #pragma unroll
            for (int j = 0; j < 8; j++) {
                float4 kv = Ks[(8 * g + j) * 32 + (c ^ g)];
                sA[j] = fmaf(aA.w, kv.w, fmaf(aA.z, kv.z,
                        fmaf(aA.y, kv.y, fmaf(aA.x, kv.x, sA[j]))));
                sB[j] = fmaf(aB.w, kv.w, fmaf(aB.z, kv.z,
                        fmaf(aB.y, kv.y, fmaf(aB.x, kv.x, sB[j]))));
            }
        }

        // ---- exchange + sorted-register insert ----
        #pragma unroll
        for (int j = 0; j < 8; j++) {
            float rA = __shfl_xor_sync(0xffffffffu, sA[j], 4);
            float rB = __shfl_xor_sync(0xffffffffu, sB[j], 4);
            float c1 = h ? sB[j] : sA[j];
            float c2 = h ? rB : rA;
            int   i1 = zbase + tile * 64 + 8 * g + j;
            int   i2 = zbase + tile * 64 + 8 * (g ^ 4) + j;
            if (c1 > fmaxf(Tsh, lv[31])) {
                bool pp = true;
                #pragma unroll
                for (int p = 31; p >= 1; p--) {
                    bool pr = lv[p - 1] < c1;
                    float nv = pr ? lv[p - 1] : (pp ? c1 : lv[p]);
                    int   ni = pr ? li[p - 1] : (pp ? i1 : li[p]);
                    lv[p] = nv; li[p] = ni;
                    pp = pr;
                }
                if (pp) { lv[0] = c1; li[0] = i1; }
            }
            if (c2 > fmaxf(Tsh, lv[31])) {
                bool pp = true;
                #pragma unroll
                for (int p = 31; p >= 1; p--) {
                    bool pr = lv[p - 1] < c2;
                    float nv = pr ? lv[p - 1] : (pp ? c2 : lv[p]);
                    int   ni = pr ? li[p - 1] : (pp ? i2 : li[p]);
                    lv[p] = nv; li[p] = ni;
                    pp = pr;
                }
                if (pp) { lv[0] = c2; li[0] = i2; }
            }
        }
        {
            float tm = lv[31];
            tm = fmaxf(tm, __shfl_xor_sync(0xffffffffu, tm, 1));
            tm = fmaxf(tm, __shfl_xor_sync(0xffffffffu, tm, 2));
            Tsh = tm;
        }
        __syncthreads();
    }

    // ---- dump lists, tournament-merge per query-half, write to global ----
    #pragma unroll
    for (int p = 0; p < 32; p++) {
        lv_s[p * 128 + t] = lv[p];
        li_s[p * 128 + t] = li[p];
    }
    __syncthreads();

    #pragma unroll
    for (int pass = 0; pass < 2; pass++) {
        const bool mine = (h == pass);
        int ptr = 0;
        const int qq = q0 + pair + (pass ? 16 : 0);
        size_t off = ((size_t)(b * TQ + qq) * 2 + z) * 32;
        for (int it = 0; it < 32; it++) {
            float bv = (mine && ptr < 32) ? lv_s[ptr * 128 + t] : -1e30f;
            int   wl = lane;
            #pragma unroll
            for (int o = 1; o < 8; o <<= 1) {
                float ov = __shfl_xor_sync(0xffffffffu, bv, o);
                int   ol = __shfl_xor_sync(0xffffffffu, wl, o);
                if (ov > bv) { bv = ov; wl = ol; }
            }
            int myi  = li_s[(ptr < 32 ? ptr : 31) * 128 + t];
            int widx = __shfl_sync(0xffffffffu, myi, wl);
            if (lane == wl) ptr++;
            if (g == 0) { g_mv[off + it] = bv; g_mi[off + it] = widx; }
        }
    }
}

// =========================================================================
// 4b) merge kernel: rank-merge 2 sorted 32-lists -> top-32, softmax,
//     gather V, gated add. One warp per query.
// =========================================================================
__global__ __launch_bounds__(256) void mem_merge_kernel(
    const float* __restrict__ mem_vals, const float* __restrict__ gate,
    float* __restrict__ out)
{
    __shared__ float sv[8][64];
    __shared__ int   si[8][64];
    __shared__ float mv[8][32];
    __shared__ int   mi[8][32];

    const int t    = threadIdx.x;
    const int wid  = t >> 5;
    const int lane = t & 31;
    const int b    = blockIdx.y;
    const int q    = blockIdx.x * 8 + wid;

    const size_t off = (size_t)(b * TQ + q) * 64;
    sv[wid][lane]      = g_mv[off + lane];
    sv[wid][lane + 32] = g_mv[off + 32 + lane];
    si[wid][lane]      = g_mi[off + lane];
    si[wid][lane + 32] = g_mi[off + 32 + lane];
    __syncwarp();

    // rank-merge (both lists sorted descending)
    float av  = sv[wid][lane];
    float bvv = sv[wid][lane + 32];
    int lo = 0, hi = 32;
    while (lo < hi) { int mid = (lo + hi) >> 1; if (sv[wid][32 + mid] > av) lo = mid + 1; else hi = mid; }
    int rA = lane + lo;
    lo = 0; hi = 32;
    while (lo < hi) { int mid = (lo + hi) >> 1; if (sv[wid][mid] >= bvv) lo = mid + 1; else hi = mid; }
    int rB = lane + lo;
    if (rA < 32) { mv[wid][rA] = av;  mi[wid][rA] = si[wid][lane]; }
    if (rB < 32) { mv[wid][rB] = bvv; mi[wid][rB] = si[wid][lane + 32]; }
    __syncwarp();

    // softmax + gather (descending order, identical arithmetic)
    const float* vb = mem_vals + (size_t)b * NM * HD;
    const float vmax = mv[wid][0];
    float sumw = 0.f;
    float4 acc = make_float4(0.f, 0.f, 0.f, 0.f);
    for (int it = 0; it < 32; it++) {
        float w = __expf((mv[wid][it] - vmax) * 0.03125f);   // 1/sqrt(1024)
        sumw += w;
        float4 vv = *(const float4*)(vb + (size_t)mi[wid][it] * HD + lane * 4);
        acc.x = fmaf(w, vv.x, acc.x);
        acc.y = fmaf(w, vv.y, acc.y);
        acc.z = fmaf(w, vv.z, acc.z);
        acc.w = fmaf(w, vv.w, acc.w);
    }

    const float sc = (1.0f - gate[0]) / sumw;
    float4* op = (float4*)(out + (size_t)(b * TQ + q) * HD + lane * 4);
    float4 o = *op;
    o.x += sc * acc.x; o.y += sc * acc.y;
    o.z += sc * acc.z; o.w += sc * acc.w;
    *op = o;
}

// =========================================================================
extern "C" void kernel_launch(void* const* d_in, const int* in_sizes, int n_in,
                              void* d_out, int out_size) {
    const float* x        = (const float*)d_in[0];
    const float* ki       = (const float*)d_in[1];
    const float* vi       = (const float*)d_in[2];
    const float* mem_keys = (const float*)d_in[3];
    const float* mem_vals = (const float*)d_in[4];
    const float* Wq       = (const float*)d_in[5];
    const float* bq       = (const float*)d_in[6];
    const float* Wk       = (const float*)d_in[7];
    const float* bk       = (const float*)d_in[8];
    const float* Wv       = (const float*)d_in[9];
    const float* bv       = (const float*)d_in[10];
    const float* gate     = (const float*)d_in[11];
    const int*   idxp     = (const int*)d_in[12];
    float* out = (float*)d_out;

    cudaFuncSetAttribute(attn_kernel, cudaFuncAttributeMaxDynamicSharedMemorySize,
                         ATTN_SMEM);
    cudaFuncSetAttribute(mem_score_kernel, cudaFuncAttributeMaxDynamicSharedMemorySize,
                         MEMS_SMEM);

    copy_prefix_kernel<<<1024, 256>>>(ki, vi, idxp);
    proj_kernel<<<dim3(128, 3), 256>>>(x, Wq, Wk, Wv, bq, bk, bv);
    attn_kernel<<<dim3(32, 4), 256, ATTN_SMEM>>>(gate, out);
    mem_score_kernel<<<dim3(64, 4, 2), 128, MEMS_SMEM>>>(mem_keys);
    mem_merge_kernel<<<dim3(256, 4), 256>>>(mem_vals, gate, out);
}

// round 11
// speedup vs baseline: 1.0074x; 1.0074x over previous
#include <cuda_runtime.h>
#include <cstdint>

#define NB   4
#define TQ   2048
#define NE   1024
#define HD   128
#define TKF  4096
#define NM   16384

typedef unsigned long long ull;

// ---------------- packed f32x2 helpers (sm_103a only) ----------------
__device__ __forceinline__ ull dup2(float x) {
    ull r; asm("mov.b64 %0, {%1, %1};" : "=l"(r) : "f"(x)); return r;
}
__device__ __forceinline__ float2 u2f(ull v) {
    float2 r; asm("mov.b64 {%0, %1}, %2;" : "=f"(r.x), "=f"(r.y) : "l"(v)); return r;
}
__device__ __forceinline__ ull ffma2(ull a, ull b, ull c) {
    ull d; asm("fma.rn.f32x2 %0, %1, %2, %3;" : "=l"(d) : "l"(a), "l"(b), "l"(c)); return d;
}
__device__ __forceinline__ ull fmul2(ull a, ull b) {
    ull d; asm("mul.rn.f32x2 %0, %1, %2;" : "=l"(d) : "l"(a), "l"(b)); return d;
}

// ---------------- cp.async helpers ----------------
__device__ __forceinline__ void cp16(uint32_t dst_smem, const void* src) {
    asm volatile("cp.async.ca.shared.global [%0], [%1], 16;"
                 :: "r"(dst_smem), "l"(src));
}
__device__ __forceinline__ void cp_commit() {
    asm volatile("cp.async.commit_group;");
}
__device__ __forceinline__ void cp_wait0() {
    asm volatile("cp.async.wait_group 0;");
}

// ---------------- device scratch ----------------
__device__ float g_q [(size_t)NB * TQ  * HD];
__device__ float g_kf[(size_t)NB * TKF * HD];
__device__ float g_vf[(size_t)NB * TKF * HD];
// top-k scratch: per query, 2 halves x top-32 (val, idx)
__device__ float g_mv[(size_t)NB * TQ * 64];
__device__ int   g_mi[(size_t)NB * TQ * 64];

// =========================================================================
// 1) prefix copy
// =========================================================================
__global__ __launch_bounds__(256) void copy_prefix_kernel(
    const float* __restrict__ ki, const float* __restrict__ vi,
    const int* __restrict__ idxp)
{
    const int s  = idxp[0] * HD;
    const int e4 = blockIdx.x * 256 + threadIdx.x;
    const int d4 = e4 & 31;
    const int t  = (e4 >> 5) & (TQ - 1);
    const int b  = e4 >> 16;
    const size_t src = ((size_t)b * TQ + t) * NE + s + (size_t)d4 * 4;
    const size_t dst = ((size_t)b * TKF + t) * HD + (size_t)d4 * 4;
    *(float4*)(g_kf + dst) = *(const float4*)(ki + src);
    *(float4*)(g_vf + dst) = *(const float4*)(vi + src);
}

// =========================================================================
// 2) fused projection GEMM (packed FFMA2) — unchanged
// =========================================================================
__global__ __launch_bounds__(256) void proj_kernel(
    const float* __restrict__ X,
    const float* __restrict__ Wq, const float* __restrict__ Wk,
    const float* __restrict__ Wv,
    const float* __restrict__ bq, const float* __restrict__ bk,
    const float* __restrict__ bv)
{
    __shared__ float As[64][17];
    __shared__ float Bs[16][128];
    const int mode = blockIdx.y;
    const float* W    = (mode == 0) ? Wq : (mode == 1) ? Wk : Wv;
    const float* bias = (mode == 0) ? bq : (mode == 1) ? bk : bv;
    float* dst        = (mode == 0) ? g_q : (mode == 1) ? g_kf : g_vf;

    const int t   = threadIdx.x;
    const int bm0 = blockIdx.x * 64;
    const int tr  = t >> 4;
    const int tc  = t & 15;

    ull acc[4][4];
    #pragma unroll
    for (int i = 0; i < 4; i++)
        #pragma unroll
        for (int j = 0; j < 4; j++) acc[i][j] = 0ULL;

    const int ar = t >> 2, ac = (t & 3) * 4;
    const int br = t >> 5, bc = (t & 31) * 4;

    for (int k0 = 0; k0 < NE; k0 += 16) {
        float4 av = *(const float4*)(X + (size_t)(bm0 + ar) * NE + k0 + ac);
        As[ar][ac + 0] = av.x; As[ar][ac + 1] = av.y;
        As[ar][ac + 2] = av.z; As[ar][ac + 3] = av.w;
        *(float4*)(&Bs[br][bc])     = *(const float4*)(W + (size_t)(k0 + br) * HD + bc);
        *(float4*)(&Bs[br + 8][bc]) = *(const float4*)(W + (size_t)(k0 + br + 8) * HD + bc);
        __syncthreads();
        #pragma unroll
        for (int kk = 0; kk < 16; kk++) {
            ull pa[4];
            #pragma unroll
            for (int i = 0; i < 4; i++) pa[i] = dup2(As[tr * 4 + i][kk]);
            ulonglong2 b01 = *(const ulonglong2*)(&Bs[kk][tc * 8]);
            ulonglong2 b23 = *(const ulonglong2*)(&Bs[kk][tc * 8 + 4]);
            #pragma unroll
            for (int i = 0; i < 4; i++) {
                acc[i][0] = ffma2(pa[i], b01.x, acc[i][0]);
                acc[i][1] = ffma2(pa[i], b01.y, acc[i][1]);
                acc[i][2] = ffma2(pa[i], b23.x, acc[i][2]);
                acc[i][3] = ffma2(pa[i], b23.y, acc[i][3]);
            }
        }
        __syncthreads();
    }

    float4 bb0 = *(const float4*)(bias + tc * 8);
    float4 bb1 = *(const float4*)(bias + tc * 8 + 4);
    #pragma unroll
    for (int i = 0; i < 4; i++) {
        int row = bm0 + tr * 4 + i;
        int bi  = row >> 11;
        int tt  = row & (TQ - 1);
        size_t orow = (mode == 0) ? (size_t)row : ((size_t)bi * TKF + TQ + tt);
        float2 a0 = u2f(acc[i][0]), a1 = u2f(acc[i][1]);
        float2 a2 = u2f(acc[i][2]), a3 = u2f(acc[i][3]);
        float4 o0 = make_float4(a0.x + bb0.x, a0.y + bb0.y, a1.x + bb0.z, a1.y + bb0.w);
        float4 o1 = make_float4(a2.x + bb1.x, a2.y + bb1.y, a3.x + bb1.z, a3.y + bb1.w);
        *(float4*)(dst + orow * HD + tc * 8)     = o0;
        *(float4*)(dst + orow * HD + tc * 8 + 4) = o1;
    }
}

// =========================================================================
// 3) causal flash attention — double-buffered cp.async (unchanged)
// =========================================================================
#define ATTN_SMEM (32768 + 65536 + 65536 + 64 * 68 * 4)

__global__ __launch_bounds__(256) void attn_kernel(
    const float* __restrict__ gate, float* __restrict__ out)
{
    extern __shared__ float smem_dyn[];
    float4* Qs  = (float4*)smem_dyn;
    float4* Ks0 = Qs + 64 * 32;
    float4* Ks1 = Ks0 + 64 * 32;
    float4* Vs0 = Ks1 + 64 * 32;
    float4* Vs1 = Vs0 + 64 * 32;
    float*  Ss  = (float*)(Vs1 + 64 * 32);

    const int t  = threadIdx.x;
    const int b  = blockIdx.y;
    const int qb = blockIdx.x;
    const int tq = t >> 4;
    const int tk = t & 15;
    const float scale = 0.08838834764831845f;

    const float4* qsrc = (const float4*)(g_q + ((size_t)(b * TQ + qb * 64)) * HD);
    #pragma unroll
    for (int i = 0; i < 8; i++) {
        int idx = t + i * 256; int r = idx >> 5, c = idx & 31;
        Qs[r * 32 + (c ^ ((r >> 2) & 7))] = qsrc[idx];
    }

    float m[4], l[4];
    ull ac2[4][4];
    #pragma unroll
    for (int i = 0; i < 4; i++) {
        m[i] = -1e30f; l[i] = 0.f;
        #pragma unroll
        for (int j = 0; j < 4; j++) ac2[i][j] = 0ULL;
    }

    const float4* kbase = (const float4*)(g_kf + ((size_t)b * TKF) * HD);
    const float4* vbase = (const float4*)(g_vf + ((size_t)b * TKF) * HD);
    const int ntiles = qb + 33;

    {
        uint32_t kd = (uint32_t)__cvta_generic_to_shared(Ks0);
        uint32_t vd = (uint32_t)__cvta_generic_to_shared(Vs0);
        #pragma unroll
        for (int i = 0; i < 8; i++) {
            int idx = t + i * 256; int r = idx >> 5, c = idx & 31;
            uint32_t off = (uint32_t)(r * 32 + (c ^ ((r >> 2) & 7))) * 16u;
            cp16(kd + off, kbase + idx);
            cp16(vd + off, vbase + idx);
        }
        cp_commit();
    }

    for (int tile = 0; tile < ntiles; tile++) {
        cp_wait0();
        __syncthreads();
        const float4* Ks = (tile & 1) ? Ks1 : Ks0;
        const float4* Vs = (tile & 1) ? Vs1 : Vs0;

        if (tile + 1 < ntiles) {
            float4* Kn = (tile & 1) ? Ks0 : Ks1;
            float4* Vn = (tile & 1) ? Vs0 : Vs1;
            uint32_t kd = (uint32_t)__cvta_generic_to_shared(Kn);
            uint32_t vd = (uint32_t)__cvta_generic_to_shared(Vn);
            const float4* ks = kbase + (size_t)(tile + 1) * 64 * 32;
            const float4* vs = vbase + (size_t)(tile + 1) * 64 * 32;
            #pragma unroll
            for (int i = 0; i < 8; i++) {
                int idx = t + i * 256; int r = idx >> 5, c = idx & 31;
                uint32_t off = (uint32_t)(r * 32 + (c ^ ((r >> 2) & 7))) * 16u;
                cp16(kd + off, ks + idx);
                cp16(vd + off, vs + idx);
            }
            cp_commit();
        }

        ull s2[4][4];
        #pragma unroll
        for (int i = 0; i < 4; i++)
            #pragma unroll
            for (int j = 0; j < 4; j++) s2[i][j] = 0ULL;

        #pragma unroll 4
        for (int c = 0; c < 32; c++) {
            ulonglong2 a2[4], k2[4];
            #pragma unroll
            for (int i = 0; i < 4; i++)
                a2[i] = *(const ulonglong2*)&Qs[(4 * tq + i) * 32 + (c ^ (tq & 7))];
            #pragma unroll
            for (int j = 0; j < 4; j++)
                k2[j] = *(const ulonglong2*)&Ks[(4 * tk + j) * 32 + (c ^ (tk & 7))];
            #pragma unroll
            for (int i = 0; i < 4; i++)
                #pragma unroll
                for (int j = 0; j < 4; j++)
                    s2[i][j] = ffma2(a2[i].x, k2[j].x,
                               ffma2(a2[i].y, k2[j].y, s2[i][j]));
        }

        float s[4][4];
        const bool lastTile = (tile == ntiles - 1);
        #pragma unroll
        for (int i = 0; i < 4; i++)
            #pragma unroll
            for (int j = 0; j < 4; j++) {
                float2 p = u2f(s2[i][j]);
                s[i][j] = (p.x + p.y) * scale;
                if (lastTile && (4 * tk + j > 4 * tq + i)) s[i][j] = -1e30f;
            }

        float tmax[4];
        #pragma unroll
        for (int i = 0; i < 4; i++)
            tmax[i] = fmaxf(fmaxf(s[i][0], s[i][1]), fmaxf(s[i][2], s[i][3]));
        #pragma unroll
        for (int o = 1; o < 16; o <<= 1)
            #pragma unroll
            for (int i = 0; i < 4; i++)
                tmax[i] = fmaxf(tmax[i], __shfl_xor_sync(0xffffffffu, tmax[i], o));

        float corr[4], rs[4];
        #pragma unroll
        for (int i = 0; i < 4; i++) {
            float mn = fmaxf(m[i], tmax[i]);
            corr[i] = __expf(m[i] - mn);
            m[i] = mn;
            rs[i] = 0.f;
            #pragma unroll
            for (int j = 0; j < 4; j++) {
                s[i][j] = __expf(s[i][j] - mn);
                rs[i] += s[i][j];
            }
        }
        #pragma unroll
        for (int o = 1; o < 16; o <<= 1)
            #pragma unroll
            for (int i = 0; i < 4; i++)
                rs[i] += __shfl_xor_sync(0xffffffffu, rs[i], o);
        #pragma unroll
        for (int i = 0; i < 4; i++) {
            l[i] = l[i] * corr[i] + rs[i];
            ull c2 = dup2(corr[i]);
            #pragma unroll
            for (int j = 0; j < 4; j++) ac2[i][j] = fmul2(ac2[i][j], c2);
            *(float4*)&Ss[(4 * tq + i) * 68 + 4 * tk] =
                make_float4(s[i][0], s[i][1], s[i][2], s[i][3]);
        }
        __syncthreads();

        #pragma unroll 2
        for (int jj = 0; jj < 16; jj++) {
            float4 p[4];
            #pragma unroll
            for (int i = 0; i < 4; i++)
                p[i] = *(const float4*)&Ss[(4 * tq + i) * 68 + jj * 4];
            #pragma unroll
            for (int e = 0; e < 4; e++) {
                int j = jj * 4 + e;
                int key = (j >> 2) & 7;
                ulonglong2 v0 = *(const ulonglong2*)&Vs[j * 32 + (tk ^ key)];
                ulonglong2 v1 = *(const ulonglong2*)&Vs[j * 32 + ((16 + tk) ^ key)];
                #pragma unroll
                for (int i = 0; i < 4; i++) {
                    float pv = (e == 0) ? p[i].x : (e == 1) ? p[i].y
                             : (e == 2) ? p[i].z : p[i].w;
                    ull pv2 = dup2(pv);
                    ac2[i][0] = ffma2(pv2, v0.x, ac2[i][0]);
                    ac2[i][1] = ffma2(pv2, v0.y, ac2[i][1]);
                    ac2[i][2] = ffma2(pv2, v1.x, ac2[i][2]);
                    ac2[i][3] = ffma2(pv2, v1.y, ac2[i][3]);
                }
            }
        }
        __syncthreads();
    }

    const float gv = gate[0];
    #pragma unroll
    for (int i = 0; i < 4; i++) {
        float inv = gv / l[i];
        size_t row = (size_t)(b * TQ + qb * 64 + 4 * tq + i) * HD;
        float2 a0 = u2f(ac2[i][0]), a1 = u2f(ac2[i][1]);
        float2 a2 = u2f(ac2[i][2]), a3 = u2f(ac2[i][3]);
        float4 o0 = make_float4(a0.x * inv, a0.y * inv, a1.x * inv, a1.y * inv);
        float4 o1 = make_float4(a2.x * inv, a2.y * inv, a3.x * inv, a3.y * inv);
        *(float4*)(out + row + 4 * tk)      = o0;
        *(float4*)(out + row + 64 + 4 * tk) = o1;
    }
}

// =========================================================================
// 4a) kNN score kernel: split-K (z=2) + double-buffered cp.async,
//     32-key tiles (48KB smem -> 3 CTAs/SM). Score chains bit-identical.
// =========================================================================
#define MEMS_SMEM 49152

__global__ __launch_bounds__(128, 3) void mem_score_kernel(
    const float* __restrict__ mem_keys)
{
    extern __shared__ float msm[];
    float4* Qs   = (float4*)msm;                  // [0, 16KB): 32q x 32 f4
    float4* Ks0  = (float4*)(msm + 4096);         // [16KB, 32KB): 32k x 32 f4
    float4* Ks1  = (float4*)(msm + 8192);         // [32KB, 48KB)
    float*  lv_s = msm;                           // overlay [0, 16KB)
    int*    li_s = (int*)(msm + 4096);            // overlay [16KB, 32KB)

    const int t    = threadIdx.x;                 // 0..127
    const int b    = blockIdx.y;
    const int q0   = blockIdx.x * 32;
    const int z    = blockIdx.z;                  // key half
    const int pair = t >> 3;                      // queries (pair, pair+16)
    const int g    = t & 7;                       // 4 keys per lane
    const int h    = g >> 2;                      // 0: owns query A, 1: owns B
    const int lane = t & 31;
    const int zbase = z * (NM / 2);

    const float4* qsrc = (const float4*)(g_q + ((size_t)(b * TQ + q0)) * HD);
    #pragma unroll
    for (int i = 0; i < 8; i++) {
        int idx = t + i * 128; int r = idx >> 5, c = idx & 31;
        Qs[r * 32 + (c ^ (r & 7))] = qsrc[idx];
    }

    float lv[32]; int li[32];
    #pragma unroll
    for (int i = 0; i < 32; i++) { lv[i] = -1e30f; li[i] = 0; }
    float Tsh = -1e30f;

    const float4* kb = (const float4*)(mem_keys + ((size_t)b * NM + zbase) * HD);
    const int NTILES = (NM / 2) / 32;             // 256

    // prefetch tile 0 (32 keys = 1024 f4, 8 per thread)
    {
        uint32_t kd = (uint32_t)__cvta_generic_to_shared(Ks0);
        #pragma unroll
        for (int i = 0; i < 8; i++) {
            int idx = t + i * 128; int r = idx >> 5, c = idx & 31;
            uint32_t off = (uint32_t)(r * 32 + (c ^ ((r >> 2) & 7))) * 16u;
            cp16(kd + off, kb + idx);
        }
        cp_commit();
    }

    for (int tile = 0; tile < NTILES; tile++) {
        cp_wait0();
        __syncthreads();
        const float4* Ks = (tile & 1) ? Ks1 : Ks0;

        if (tile + 1 < NTILES) {
            float4* Kn = (tile & 1) ? Ks0 : Ks1;
            uint32_t kd = (uint32_t)__cvta_generic_to_shared(Kn);
            const float4* ks = kb + (size_t)(tile + 1) * 1024;
            #pragma unroll
            for (int i = 0; i < 8; i++) {
                int idx = t + i * 128; int r = idx >> 5, c = idx & 31;
                uint32_t off = (uint32_t)(r * 32 + (c ^ ((r >> 2) & 7))) * 16u;
                cp16(kd + off, ks + idx);
            }
            cp_commit();
        }

        // ---- scores for BOTH queries; chains bit-identical per key ----
        float sA[4], sB[4];
        #pragma unroll
        for (int j = 0; j < 4; j++) { sA[j] = 0.f; sB[j] = 0.f; }
        #pragma unroll 4
        for (int c = 0; c < 32; c++) {
            float4 aA = Qs[pair * 32 + (c ^ (pair & 7))];
            float4 aB = Qs[(pair + 16) * 32 + (c ^ (pair & 7))];
            #pragma unroll
            for (int j = 0; j < 4; j++) {
                float4 kv = Ks[(4 * g + j) * 32 + (c ^ g)];
                sA[j] = fmaf(aA.w, kv.w, fmaf(aA.z, kv.z,
                        fmaf(aA.y, kv.y, fmaf(aA.x, kv.x, sA[j]))));
                sB[j] = fmaf(aB.w, kv.w, fmaf(aB.z, kv.z,
                        fmaf(aB.y, kv.y, fmaf(aB.x, kv.x, sB[j]))));
            }
        }

        // ---- exchange halves; each lane owns ONE query's candidates ----
        #pragma unroll
        for (int j = 0; j < 4; j++) {
            float rA = __shfl_xor_sync(0xffffffffu, sA[j], 4);
            float rB = __shfl_xor_sync(0xffffffffu, sB[j], 4);
            float c1 = h ? sB[j] : sA[j];
            float c2 = h ? rB : rA;
            int   i1 = zbase + tile * 32 + 4 * g + j;
            int   i2 = zbase + tile * 32 + 4 * (g ^ 4) + j;
            if (c1 > fmaxf(Tsh, lv[31])) {
                bool pp = true;
                #pragma unroll
                for (int p = 31; p >= 1; p--) {
                    bool pr = lv[p - 1] < c1;
                    float nv = pr ? lv[p - 1] : (pp ? c1 : lv[p]);
                    int   ni = pr ? li[p - 1] : (pp ? i1 : li[p]);
                    lv[p] = nv; li[p] = ni;
                    pp = pr;
                }
                if (pp) { lv[0] = c1; li[0] = i1; }
            }
            if (c2 > fmaxf(Tsh, lv[31])) {
                bool pp = true;
                #pragma unroll
                for (int p = 31; p >= 1; p--) {
                    bool pr = lv[p - 1] < c2;
                    float nv = pr ? lv[p - 1] : (pp ? c2 : lv[p]);
                    int   ni = pr ? li[p - 1] : (pp ? i2 : li[p]);
                    lv[p] = nv; li[p] = ni;
                    pp = pr;
                }
                if (pp) { lv[0] = c2; li[0] = i2; }
            }
        }
        {
            float tm = lv[31];
            tm = fmaxf(tm, __shfl_xor_sync(0xffffffffu, tm, 1));
            tm = fmaxf(tm, __shfl_xor_sync(0xffffffffu, tm, 2));
            Tsh = tm;
        }
        __syncthreads();
    }

    // ---- dump lists, tournament-merge per query, write to global ----
    #pragma unroll
    for (int p = 0; p < 32; p++) {
        lv_s[p * 128 + t] = lv[p];
        li_s[p * 128 + t] = li[p];
    }
    __syncthreads();

    #pragma unroll
    for (int pass = 0; pass < 2; pass++) {
        const bool mine = (h == pass);
        int ptr = 0;
        const int qq = q0 + pair + (pass ? 16 : 0);
        size_t off = ((size_t)(b * TQ + qq) * 2 + z) * 32;
        for (int it = 0; it < 32; it++) {
            float bv = (mine && ptr < 32) ? lv_s[ptr * 128 + t] : -1e30f;
            int   wl = lane;
            #pragma unroll
            for (int o = 1; o < 8; o <<= 1) {
                float ov = __shfl_xor_sync(0xffffffffu, bv, o);
                int   ol = __shfl_xor_sync(0xffffffffu, wl, o);
                if (ov > bv) { bv = ov; wl = ol; }
            }
            int myi  = li_s[(ptr < 32 ? ptr : 31) * 128 + t];
            int widx = __shfl_sync(0xffffffffu, myi, wl);
            if (lane == wl) ptr++;
            if (g == 0) { g_mv[off + it] = bv; g_mi[off + it] = widx; }
        }
    }
}

// =========================================================================
// 4b) merge kernel: rank-merge 2 sorted 32-lists -> top-32, softmax,
//     gather V, gated add. One warp per query. (proven in R10)
// =========================================================================
__global__ __launch_bounds__(256) void mem_merge_kernel(
    const float* __restrict__ mem_vals, const float* __restrict__ gate,
    float* __restrict__ out)
{
    __shared__ float sv[8][64];
    __shared__ int   si[8][64];
    __shared__ float mv[8][32];
    __shared__ int   mi[8][32];

    const int t    = threadIdx.x;
    const int wid  = t >> 5;
    const int lane = t & 31;
    const int b    = blockIdx.y;
    const int q    = blockIdx.x * 8 + wid;

    const size_t off = (size_t)(b * TQ + q) * 64;
    sv[wid][lane]      = g_mv[off + lane];
    sv[wid][lane + 32] = g_mv[off + 32 + lane];
    si[wid][lane]      = g_mi[off + lane];
    si[wid][lane + 32] = g_mi[off + 32 + lane];
    __syncwarp();

    float av  = sv[wid][lane];
    float bvv = sv[wid][lane + 32];
    int lo = 0, hi = 32;
    while (lo < hi) { int mid = (lo + hi) >> 1; if (sv[wid][32 + mid] > av) lo = mid + 1; else hi = mid; }
    int rA = lane + lo;
    lo = 0; hi = 32;
    while (lo < hi) { int mid = (lo + hi) >> 1; if (sv[wid][mid] >= bvv) lo = mid + 1; else hi = mid; }
    int rB = lane + lo;
    if (rA < 32) { mv[wid][rA] = av;  mi[wid][rA] = si[wid][lane]; }
    if (rB < 32) { mv[wid][rB] = bvv; mi[wid][rB] = si[wid][lane + 32]; }
    __syncwarp();

    const float* vb = mem_vals + (size_t)b * NM * HD;
    const float vmax = mv[wid][0];
    float sumw = 0.f;
    float4 acc = make_float4(0.f, 0.f, 0.f, 0.f);
    for (int it = 0; it < 32; it++) {
        float w = __expf((mv[wid][it] - vmax) * 0.03125f);   // 1/sqrt(1024)
        sumw += w;
        float4 vv = *(const float4*)(vb + (size_t)mi[wid][it] * HD + lane * 4);
        acc.x = fmaf(w, vv.x, acc.x);
        acc.y = fmaf(w, vv.y, acc.y);
        acc.z = fmaf(w, vv.z, acc.z);
        acc.w = fmaf(w, vv.w, acc.w);
    }

    const float sc = (1.0f - gate[0]) / sumw;
    float4* op = (float4*)(out + (size_t)(b * TQ + q) * HD + lane * 4);
    float4 o = *op;
    o.x += sc * acc.x; o.y += sc * acc.y;
    o.z += sc * acc.z; o.w += sc * acc.w;
    *op = o;
}

// =========================================================================
extern "C" void kernel_launch(void* const* d_in, const int* in_sizes, int n_in,
                              void* d_out, int out_size) {
    const float* x        = (const float*)d_in[0];
    const float* ki       = (const float*)d_in[1];
    const float* vi       = (const float*)d_in[2];
    const float* mem_keys = (const float*)d_in[3];
    const float* mem_vals = (const float*)d_in[4];
    const float* Wq       = (const float*)d_in[5];
    const float* bq       = (const float*)d_in[6];
    const float* Wk       = (const float*)d_in[7];
    const float* bk       = (const float*)d_in[8];
    const float* Wv       = (const float*)d_in[9];
    const float* bv       = (const float*)d_in[10];
    const float* gate     = (const float*)d_in[11];
    const int*   idxp     = (const int*)d_in[12];
    float* out = (float*)d_out;

    cudaFuncSetAttribute(attn_kernel, cudaFuncAttributeMaxDynamicSharedMemorySize,
                         ATTN_SMEM);
    cudaFuncSetAttribute(mem_score_kernel, cudaFuncAttributeMaxDynamicSharedMemorySize,
                         MEMS_SMEM);

    copy_prefix_kernel<<<1024, 256>>>(ki, vi, idxp);
    proj_kernel<<<dim3(128, 3), 256>>>(x, Wq, Wk, Wv, bq, bk, bv);
    attn_kernel<<<dim3(32, 4), 256, ATTN_SMEM>>>(gate, out);
    mem_score_kernel<<<dim3(64, 4, 2), 128, MEMS_SMEM>>>(mem_keys);
    mem_merge_kernel<<<dim3(256, 4), 256>>>(mem_vals, gate, out);
}

// round 12
// speedup vs baseline: 1.0976x; 1.0895x over previous
#include <cuda_runtime.h>
#include <cstdint>

#define NB   4
#define TQ   2048
#define NE   1024
#define HD   128
#define TKF  4096
#define NM   16384

typedef unsigned long long ull;

// ---------------- packed f32x2 helpers (sm_103a only) ----------------
__device__ __forceinline__ ull dup2(float x) {
    ull r; asm("mov.b64 %0, {%1, %1};" : "=l"(r) : "f"(x)); return r;
}
__device__ __forceinline__ float2 u2f(ull v) {
    float2 r; asm("mov.b64 {%0, %1}, %2;" : "=f"(r.x), "=f"(r.y) : "l"(v)); return r;
}
__device__ __forceinline__ ull ffma2(ull a, ull b, ull c) {
    ull d; asm("fma.rn.f32x2 %0, %1, %2, %3;" : "=l"(d) : "l"(a), "l"(b), "l"(c)); return d;
}
__device__ __forceinline__ ull fmul2(ull a, ull b) {
    ull d; asm("mul.rn.f32x2 %0, %1, %2;" : "=l"(d) : "l"(a), "l"(b)); return d;
}

// ---------------- cp.async helpers ----------------
__device__ __forceinline__ void cp16(uint32_t dst_smem, const void* src) {
    asm volatile("cp.async.ca.shared.global [%0], [%1], 16;"
                 :: "r"(dst_smem), "l"(src));
}
__device__ __forceinline__ void cp_commit() {
    asm volatile("cp.async.commit_group;");
}
__device__ __forceinline__ void cp_wait0() {
    asm volatile("cp.async.wait_group 0;");
}

// ---------------- device scratch ----------------
__device__ float g_q [(size_t)NB * TQ  * HD];
__device__ float g_kf[(size_t)NB * TKF * HD];
__device__ float g_vf[(size_t)NB * TKF * HD];
// key-pair-interleaved copy of mem_keys:
// g_ki[((b*8192 + p)*128 + d)*2 + e] = mem_keys[b][2p+e][d]
__device__ float g_ki[(size_t)NB * NM * HD];

// =========================================================================
// 0) key interleave pre-pass: pack key pairs along dims
// =========================================================================
__global__ __launch_bounds__(256) void interleave_kernel(
    const float* __restrict__ mem_keys)
{
    const int f4 = blockIdx.x * 256 + threadIdx.x;   // 0 .. 2M-1
    const int d2 = f4 & 63;
    const int p  = (f4 >> 6) & 8191;
    const int b  = f4 >> 19;
    const float2* r0 = (const float2*)(mem_keys + ((size_t)b * NM + 2 * p)     * HD) + d2;
    const float2* r1 = (const float2*)(mem_keys + ((size_t)b * NM + 2 * p + 1) * HD) + d2;
    float2 a = *r0, c = *r1;
    ((float4*)g_ki)[f4] = make_float4(a.x, c.x, a.y, c.y);
}

// =========================================================================
// 1) prefix copy
// =========================================================================
__global__ __launch_bounds__(256) void copy_prefix_kernel(
    const float* __restrict__ ki, const float* __restrict__ vi,
    const int* __restrict__ idxp)
{
    const int s  = idxp[0] * HD;
    const int e4 = blockIdx.x * 256 + threadIdx.x;
    const int d4 = e4 & 31;
    const int t  = (e4 >> 5) & (TQ - 1);
    const int b  = e4 >> 16;
    const size_t src = ((size_t)b * TQ + t) * NE + s + (size_t)d4 * 4;
    const size_t dst = ((size_t)b * TKF + t) * HD + (size_t)d4 * 4;
    *(float4*)(g_kf + dst) = *(const float4*)(ki + src);
    *(float4*)(g_vf + dst) = *(const float4*)(vi + src);
}

// =========================================================================
// 2) fused projection GEMM (packed FFMA2) — unchanged
// =========================================================================
__global__ __launch_bounds__(256) void proj_kernel(
    const float* __restrict__ X,
    const float* __restrict__ Wq, const float* __restrict__ Wk,
    const float* __restrict__ Wv,
    const float* __restrict__ bq, const float* __restrict__ bk,
    const float* __restrict__ bv)
{
    __shared__ float As[64][17];
    __shared__ float Bs[16][128];
    const int mode = blockIdx.y;
    const float* W    = (mode == 0) ? Wq : (mode == 1) ? Wk : Wv;
    const float* bias = (mode == 0) ? bq : (mode == 1) ? bk : bv;
    float* dst        = (mode == 0) ? g_q : (mode == 1) ? g_kf : g_vf;

    const int t   = threadIdx.x;
    const int bm0 = blockIdx.x * 64;
    const int tr  = t >> 4;
    const int tc  = t & 15;

    ull acc[4][4];
    #pragma unroll
    for (int i = 0; i < 4; i++)
        #pragma unroll
        for (int j = 0; j < 4; j++) acc[i][j] = 0ULL;

    const int ar = t >> 2, ac = (t & 3) * 4;
    const int br = t >> 5, bc = (t & 31) * 4;

    for (int k0 = 0; k0 < NE; k0 += 16) {
        float4 av = *(const float4*)(X + (size_t)(bm0 + ar) * NE + k0 + ac);
        As[ar][ac + 0] = av.x; As[ar][ac + 1] = av.y;
        As[ar][ac + 2] = av.z; As[ar][ac + 3] = av.w;
        *(float4*)(&Bs[br][bc])     = *(const float4*)(W + (size_t)(k0 + br) * HD + bc);
        *(float4*)(&Bs[br + 8][bc]) = *(const float4*)(W + (size_t)(k0 + br + 8) * HD + bc);
        __syncthreads();
        #pragma unroll
        for (int kk = 0; kk < 16; kk++) {
            ull pa[4];
            #pragma unroll
            for (int i = 0; i < 4; i++) pa[i] = dup2(As[tr * 4 + i][kk]);
            ulonglong2 b01 = *(const ulonglong2*)(&Bs[kk][tc * 8]);
            ulonglong2 b23 = *(const ulonglong2*)(&Bs[kk][tc * 8 + 4]);
            #pragma unroll
            for (int i = 0; i < 4; i++) {
                acc[i][0] = ffma2(pa[i], b01.x, acc[i][0]);
                acc[i][1] = ffma2(pa[i], b01.y, acc[i][1]);
                acc[i][2] = ffma2(pa[i], b23.x, acc[i][2]);
                acc[i][3] = ffma2(pa[i], b23.y, acc[i][3]);
            }
        }
        __syncthreads();
    }

    float4 bb0 = *(const float4*)(bias + tc * 8);
    float4 bb1 = *(const float4*)(bias + tc * 8 + 4);
    #pragma unroll
    for (int i = 0; i < 4; i++) {
        int row = bm0 + tr * 4 + i;
        int bi  = row >> 11;
        int tt  = row & (TQ - 1);
        size_t orow = (mode == 0) ? (size_t)row : ((size_t)bi * TKF + TQ + tt);
        float2 a0 = u2f(acc[i][0]), a1 = u2f(acc[i][1]);
        float2 a2 = u2f(acc[i][2]), a3 = u2f(acc[i][3]);
        float4 o0 = make_float4(a0.x + bb0.x, a0.y + bb0.y, a1.x + bb0.z, a1.y + bb0.w);
        float4 o1 = make_float4(a2.x + bb1.x, a2.y + bb1.y, a3.x + bb1.z, a3.y + bb1.w);
        *(float4*)(dst + orow * HD + tc * 8)     = o0;
        *(float4*)(dst + orow * HD + tc * 8 + 4) = o1;
    }
}

// =========================================================================
// 3) causal flash attention — double-buffered cp.async (unchanged from R9)
// =========================================================================
#define ATTN_SMEM (32768 + 65536 + 65536 + 64 * 68 * 4)

__global__ __launch_bounds__(256) void attn_kernel(
    const float* __restrict__ gate, float* __restrict__ out)
{
    extern __shared__ float smem_dyn[];
    float4* Qs  = (float4*)smem_dyn;
    float4* Ks0 = Qs + 64 * 32;
    float4* Ks1 = Ks0 + 64 * 32;
    float4* Vs0 = Ks1 + 64 * 32;
    float4* Vs1 = Vs0 + 64 * 32;
    float*  Ss  = (float*)(Vs1 + 64 * 32);

    const int t  = threadIdx.x;
    const int b  = blockIdx.y;
    const int qb = blockIdx.x;
    const int tq = t >> 4;
    const int tk = t & 15;
    const float scale = 0.08838834764831845f;

    const float4* qsrc = (const float4*)(g_q + ((size_t)(b * TQ + qb * 64)) * HD);
    #pragma unroll
    for (int i = 0; i < 8; i++) {
        int idx = t + i * 256; int r = idx >> 5, c = idx & 31;
        Qs[r * 32 + (c ^ ((r >> 2) & 7))] = qsrc[idx];
    }

    float m[4], l[4];
    ull ac2[4][4];
    #pragma unroll
    for (int i = 0; i < 4; i++) {
        m[i] = -1e30f; l[i] = 0.f;
        #pragma unroll
        for (int j = 0; j < 4; j++) ac2[i][j] = 0ULL;
    }

    const float4* kbase = (const float4*)(g_kf + ((size_t)b * TKF) * HD);
    const float4* vbase = (const float4*)(g_vf + ((size_t)b * TKF) * HD);
    const int ntiles = qb + 33;

    {
        uint32_t kd = (uint32_t)__cvta_generic_to_shared(Ks0);
        uint32_t vd = (uint32_t)__cvta_generic_to_shared(Vs0);
        #pragma unroll
        for (int i = 0; i < 8; i++) {
            int idx = t + i * 256; int r = idx >> 5, c = idx & 31;
            uint32_t off = (uint32_t)(r * 32 + (c ^ ((r >> 2) & 7))) * 16u;
            cp16(kd + off, kbase + idx);
            cp16(vd + off, vbase + idx);
        }
        cp_commit();
    }

    for (int tile = 0; tile < ntiles; tile++) {
        cp_wait0();
        __syncthreads();
        const float4* Ks = (tile & 1) ? Ks1 : Ks0;
        const float4* Vs = (tile & 1) ? Vs1 : Vs0;

        if (tile + 1 < ntiles) {
            float4* Kn = (tile & 1) ? Ks0 : Ks1;
            float4* Vn = (tile & 1) ? Vs0 : Vs1;
            uint32_t kd = (uint32_t)__cvta_generic_to_shared(Kn);
            uint32_t vd = (uint32_t)__cvta_generic_to_shared(Vn);
            const float4* ks = kbase + (size_t)(tile + 1) * 64 * 32;
            const float4* vs = vbase + (size_t)(tile + 1) * 64 * 32;
            #pragma unroll
            for (int i = 0; i < 8; i++) {
                int idx = t + i * 256; int r = idx >> 5, c = idx & 31;
                uint32_t off = (uint32_t)(r * 32 + (c ^ ((r >> 2) & 7))) * 16u;
                cp16(kd + off, ks + idx);
                cp16(vd + off, vs + idx);
            }
            cp_commit();
        }

        ull s2[4][4];
        #pragma unroll
        for (int i = 0; i < 4; i++)
            #pragma unroll
            for (int j = 0; j < 4; j++) s2[i][j] = 0ULL;

        #pragma unroll 4
        for (int c = 0; c < 32; c++) {
            ulonglong2 a2[4], k2[4];
            #pragma unroll
            for (int i = 0; i < 4; i++)
                a2[i] = *(const ulonglong2*)&Qs[(4 * tq + i) * 32 + (c ^ (tq & 7))];
            #pragma unroll
            for (int j = 0; j < 4; j++)
                k2[j] = *(const ulonglong2*)&Ks[(4 * tk + j) * 32 + (c ^ (tk & 7))];
            #pragma unroll
            for (int i = 0; i < 4; i++)
                #pragma unroll
                for (int j = 0; j < 4; j++)
                    s2[i][j] = ffma2(a2[i].x, k2[j].x,
                               ffma2(a2[i].y, k2[j].y, s2[i][j]));
        }

        float s[4][4];
        const bool lastTile = (tile == ntiles - 1);
        #pragma unroll
        for (int i = 0; i < 4; i++)
            #pragma unroll
            for (int j = 0; j < 4; j++) {
                float2 p = u2f(s2[i][j]);
                s[i][j] = (p.x + p.y) * scale;
                if (lastTile && (4 * tk + j > 4 * tq + i)) s[i][j] = -1e30f;
            }

        float tmax[4];
        #pragma unroll
        for (int i = 0; i < 4; i++)
            tmax[i] = fmaxf(fmaxf(s[i][0], s[i][1]), fmaxf(s[i][2], s[i][3]));
        #pragma unroll
        for (int o = 1; o < 16; o <<= 1)
            #pragma unroll
            for (int i = 0; i < 4; i++)
                tmax[i] = fmaxf(tmax[i], __shfl_xor_sync(0xffffffffu, tmax[i], o));

        float corr[4], rs[4];
        #pragma unroll
        for (int i = 0; i < 4; i++) {
            float mn = fmaxf(m[i], tmax[i]);
            corr[i] = __expf(m[i] - mn);
            m[i] = mn;
            rs[i] = 0.f;
            #pragma unroll
            for (int j = 0; j < 4; j++) {
                s[i][j] = __expf(s[i][j] - mn);
                rs[i] += s[i][j];
            }
        }
        #pragma unroll
        for (int o = 1; o < 16; o <<= 1)
            #pragma unroll
            for (int i = 0; i < 4; i++)
                rs[i] += __shfl_xor_sync(0xffffffffu, rs[i], o);
        #pragma unroll
        for (int i = 0; i < 4; i++) {
            l[i] = l[i] * corr[i] + rs[i];
            ull c2 = dup2(corr[i]);
            #pragma unroll
            for (int j = 0; j < 4; j++) ac2[i][j] = fmul2(ac2[i][j], c2);
            *(float4*)&Ss[(4 * tq + i) * 68 + 4 * tk] =
                make_float4(s[i][0], s[i][1], s[i][2], s[i][3]);
        }
        __syncthreads();

        #pragma unroll 2
        for (int jj = 0; jj < 16; jj++) {
            float4 p[4];
            #pragma unroll
            for (int i = 0; i < 4; i++)
                p[i] = *(const float4*)&Ss[(4 * tq + i) * 68 + jj * 4];
            #pragma unroll
            for (int e = 0; e < 4; e++) {
                int j = jj * 4 + e;
                int key = (j >> 2) & 7;
                ulonglong2 v0 = *(const ulonglong2*)&Vs[j * 32 + (tk ^ key)];
                ulonglong2 v1 = *(const ulonglong2*)&Vs[j * 32 + ((16 + tk) ^ key)];
                #pragma unroll
                for (int i = 0; i < 4; i++) {
                    float pv = (e == 0) ? p[i].x : (e == 1) ? p[i].y
                             : (e == 2) ? p[i].z : p[i].w;
                    ull pv2 = dup2(pv);
                    ac2[i][0] = ffma2(pv2, v0.x, ac2[i][0]);
                    ac2[i][1] = ffma2(pv2, v0.y, ac2[i][1]);
                    ac2[i][2] = ffma2(pv2, v1.x, ac2[i][2]);
                    ac2[i][3] = ffma2(pv2, v1.y, ac2[i][3]);
                }
            }
        }
        __syncthreads();
    }

    const float gv = gate[0];
    #pragma unroll
    for (int i = 0; i < 4; i++) {
        float inv = gv / l[i];
        size_t row = (size_t)(b * TQ + qb * 64 + 4 * tq + i) * HD;
        float2 a0 = u2f(ac2[i][0]), a1 = u2f(ac2[i][1]);
        float2 a2 = u2f(ac2[i][2]), a3 = u2f(ac2[i][3]);
        float4 o0 = make_float4(a0.x * inv, a0.y * inv, a1.x * inv, a1.y * inv);
        float4 o1 = make_float4(a2.x * inv, a2.y * inv, a3.x * inv, a3.y * inv);
        *(float4*)(out + row + 4 * tk)      = o0;
        *(float4*)(out + row + 64 + 4 * tk) = o1;
    }
}

// =========================================================================
// 4) kNN memory attention v4 (R9 structure): key-pair-packed FFMA2 scores
//    (each key's chain bit-identical to R9's scalar chain), double-buffered
//    cp.async from g_ki, R9 selection/merge/gather verbatim.
// =========================================================================
#define MEM_SMEM (81920)

__global__ __launch_bounds__(128, 2) void mem_kernel(
    const float* __restrict__ mem_vals,
    const float* __restrict__ gate, float* __restrict__ out)
{
    extern __shared__ float msm[];
    float4* Qs  = (float4*)msm;                   // [0, 16KB): 32q x 32 f4
    float4* Ks0 = (float4*)(msm + 4096);          // [16KB, 48KB): 32 pairs x 64 f4
    float4* Ks1 = (float4*)(msm + 12288);         // [48KB, 80KB)
    float*  lv_s = msm;                           // overlay [0, 16KB)
    int*    li_s = (int*)(msm + 4096);            // overlay [16KB, 32KB)

    const int t    = threadIdx.x;                 // 0..127
    const int b    = blockIdx.y;
    const int q0   = blockIdx.x * 32;
    const int tq   = t >> 3;                      // queries (tq, tq+16)
    const int g    = t & 7;                       // pairs 4g..4g+3 (keys 8g..8g+7)
    const int h    = g >> 2;
    const int lane = t & 31;

    const float4* qsrc = (const float4*)(g_q + ((size_t)(b * TQ + q0)) * HD);
    #pragma unroll
    for (int i = 0; i < 8; i++) {
        int idx = t + i * 128; int r = idx >> 5, c = idx & 31;
        Qs[r * 32 + (c ^ (r & 7))] = qsrc[idx];
    }

    float lv[32]; int li[32];
    #pragma unroll
    for (int i = 0; i < 32; i++) { lv[i] = -1e30f; li[i] = 0; }
    float Tsh = -1e30f;

    // interleaved keys: tile = 32 pairs x 64 f4 = 2048 f4
    const float4* kb = (const float4*)g_ki + (size_t)b * 8192 * 64;

    // prefetch tile 0
    {
        uint32_t kd = (uint32_t)__cvta_generic_to_shared(Ks0);
        #pragma unroll
        for (int i = 0; i < 16; i++) {
            int idx = t + i * 128; int row = idx >> 6, col = idx & 63;
            uint32_t off = (uint32_t)(row * 64 + (col ^ (row >> 2))) * 16u;
            cp16(kd + off, kb + idx);
        }
        cp_commit();
    }

    for (int tile = 0; tile < NM / 64; tile++) {
        cp_wait0();
        __syncthreads();
        const float4* Ks = (tile & 1) ? Ks1 : Ks0;

        if (tile + 1 < NM / 64) {
            float4* Kn = (tile & 1) ? Ks0 : Ks1;
            uint32_t kd = (uint32_t)__cvta_generic_to_shared(Kn);
            const float4* ks = kb + (size_t)(tile + 1) * 2048;
            #pragma unroll
            for (int i = 0; i < 16; i++) {
                int idx = t + i * 128; int row = idx >> 6, col = idx & 63;
                uint32_t off = (uint32_t)(row * 64 + (col ^ (row >> 2))) * 16u;
                cp16(kd + off, ks + idx);
            }
            cp_commit();
        }

        // ---- scores: packed over key pairs; per-key chains bit-identical ----
        ull acc[2][4];                            // [query A/B][pair j]
        #pragma unroll
        for (int j = 0; j < 4; j++) { acc[0][j] = 0ULL; acc[1][j] = 0ULL; }

        #pragma unroll 4
        for (int c = 0; c < 32; c++) {
            float4 aA = Qs[tq * 32 + (c ^ (tq & 7))];
            float4 aB = Qs[(tq + 16) * 32 + (c ^ (tq & 7))];
            ull axA = dup2(aA.x), ayA = dup2(aA.y), azA = dup2(aA.z), awA = dup2(aA.w);
            ull axB = dup2(aB.x), ayB = dup2(aB.y), azB = dup2(aB.z), awB = dup2(aB.w);
            #pragma unroll
            for (int j = 0; j < 4; j++) {
                int row  = 4 * g + j;
                int base = row * 64;
                // original col4 2c, 2c+1; physical col = col4 ^ (row>>2)=g
                ulonglong2 k01 = *(const ulonglong2*)&Ks[base + ((2 * c)     ^ g)];
                ulonglong2 k23 = *(const ulonglong2*)&Ks[base + ((2 * c + 1) ^ g)];
                acc[0][j] = ffma2(axA, k01.x, acc[0][j]);
                acc[0][j] = ffma2(ayA, k01.y, acc[0][j]);
                acc[0][j] = ffma2(azA, k23.x, acc[0][j]);
                acc[0][j] = ffma2(awA, k23.y, acc[0][j]);
                acc[1][j] = ffma2(axB, k01.x, acc[1][j]);
                acc[1][j] = ffma2(ayB, k01.y, acc[1][j]);
                acc[1][j] = ffma2(azB, k23.x, acc[1][j]);
                acc[1][j] = ffma2(awB, k23.y, acc[1][j]);
            }
        }

        // unpack: key jj = 2*(jj>>1) + (jj&1); lane0 of pack = even key
        float sA[8], sB[8];
        #pragma unroll
        for (int j = 0; j < 4; j++) {
            float2 pa = u2f(acc[0][j]);
            float2 pb = u2f(acc[1][j]);
            sA[2 * j] = pa.x; sA[2 * j + 1] = pa.y;
            sB[2 * j] = pb.x; sB[2 * j + 1] = pb.y;
        }

        // ---- exchange halves; each lane owns ONE query (R9 verbatim) ----
        #pragma unroll
        for (int j = 0; j < 8; j++) {
            float rA = __shfl_xor_sync(0xffffffffu, sA[j], 4);
            float rB = __shfl_xor_sync(0xffffffffu, sB[j], 4);
            float c1 = h ? sB[j] : sA[j];
            float c2 = h ? rB : rA;
            int   i1 = tile * 64 + 8 * g + j;
            int   i2 = tile * 64 + 8 * (g ^ 4) + j;
            if (c1 > fmaxf(Tsh, lv[31])) {
                bool pp = true;
                #pragma unroll
                for (int p = 31; p >= 1; p--) {
                    bool pr = lv[p - 1] < c1;
                    float nv = pr ? lv[p - 1] : (pp ? c1 : lv[p]);
                    int   ni = pr ? li[p - 1] : (pp ? i1 : li[p]);
                    lv[p] = nv; li[p] = ni;
                    pp = pr;
                }
                if (pp) { lv[0] = c1; li[0] = i1; }
            }
            if (c2 > fmaxf(Tsh, lv[31])) {
                bool pp = true;
                #pragma unroll
                for (int p = 31; p >= 1; p--) {
                    bool pr = lv[p - 1] < c2;
                    float nv = pr ? lv[p - 1] : (pp ? c2 : lv[p]);
                    int   ni = pr ? li[p - 1] : (pp ? i2 : li[p]);
                    lv[p] = nv; li[p] = ni;
                    pp = pr;
                }
                if (pp) { lv[0] = c2; li[0] = i2; }
            }
        }
        {
            float tm = lv[31];
            tm = fmaxf(tm, __shfl_xor_sync(0xffffffffu, tm, 1));
            tm = fmaxf(tm, __shfl_xor_sync(0xffffffffu, tm, 2));
            Tsh = tm;
        }
        __syncthreads();
    }

    // ---- dump sorted lists to smem (tiles/Q dead) ----
    #pragma unroll
    for (int p = 0; p < 32; p++) {
        lv_s[p * 128 + t] = lv[p];
        li_s[p * 128 + t] = li[p];
    }
    __syncthreads();

    // ---- two merge passes: pass 0 = query A, pass 1 = B (R9 verbatim) ----
    const float* vb = mem_vals + (size_t)b * NM * HD;
    const float scg = 1.0f - gate[0];

    #pragma unroll
    for (int pass = 0; pass < 2; pass++) {
        const bool mine = (h == pass);
        float accv[16];
        #pragma unroll
        for (int u = 0; u < 16; u++) accv[u] = 0.f;
        float sumw = 0.f, vmax = 0.f;
        int ptr = 0;

        for (int it = 0; it < 32; it++) {
            float bv = (mine && ptr < 32) ? lv_s[ptr * 128 + t] : -1e30f;
            int   wl = lane;
            #pragma unroll
            for (int o = 1; o < 8; o <<= 1) {
                float ov = __shfl_xor_sync(0xffffffffu, bv, o);
                int   ol = __shfl_xor_sync(0xffffffffu, wl, o);
                if (ov > bv) { bv = ov; wl = ol; }
            }
            int myi  = li_s[(ptr < 32 ? ptr : 31) * 128 + t];
            int widx = __shfl_sync(0xffffffffu, myi, wl);
            if (lane == wl) ptr++;
            if (it == 0) vmax = bv;
            float w = __expf((bv - vmax) * 0.03125f);   // 1/sqrt(1024)
            sumw += w;
            const float4* vrow = (const float4*)(vb + (size_t)widx * HD) + g * 4;
            #pragma unroll
            for (int u = 0; u < 4; u++) {
                float4 vv = vrow[u];
                accv[4 * u + 0] = fmaf(w, vv.x, accv[4 * u + 0]);
                accv[4 * u + 1] = fmaf(w, vv.y, accv[4 * u + 1]);
                accv[4 * u + 2] = fmaf(w, vv.z, accv[4 * u + 2]);
                accv[4 * u + 3] = fmaf(w, vv.w, accv[4 * u + 3]);
            }
        }

        const float sc = scg / sumw;
        const int   qq = q0 + tq + (pass ? 16 : 0);
        float* orow = out + ((size_t)(b * TQ + qq)) * HD + g * 16;
        #pragma unroll
        for (int u = 0; u < 4; u++) {
            float4 o = ((float4*)orow)[u];
            o.x += sc * accv[4 * u + 0];
            o.y += sc * accv[4 * u + 1];
            o.z += sc * accv[4 * u + 2];
            o.w += sc * accv[4 * u + 3];
            ((float4*)orow)[u] = o;
        }
    }
}

// =========================================================================
extern "C" void kernel_launch(void* const* d_in, const int* in_sizes, int n_in,
                              void* d_out, int out_size) {
    const float* x        = (const float*)d_in[0];
    const float* ki       = (const float*)d_in[1];
    const float* vi       = (const float*)d_in[2];
    const float* mem_keys = (const float*)d_in[3];
    const float* mem_vals = (const float*)d_in[4];
    const float* Wq       = (const float*)d_in[5];
    const float* bq       = (const float*)d_in[6];
    const float* Wk       = (const float*)d_in[7];
    const float* bk       = (const float*)d_in[8];
    const float* Wv       = (const float*)d_in[9];
    const float* bv       = (const float*)d_in[10];
    const float* gate     = (const float*)d_in[11];
    const int*   idxp     = (const int*)d_in[12];
    float* out = (float*)d_out;

    cudaFuncSetAttribute(attn_kernel, cudaFuncAttributeMaxDynamicSharedMemorySize,
                         ATTN_SMEM);
    cudaFuncSetAttribute(mem_kernel, cudaFuncAttributeMaxDynamicSharedMemorySize,
                         MEM_SMEM);

    interleave_kernel<<<8192, 256>>>(mem_keys);
    copy_prefix_kernel<<<1024, 256>>>(ki, vi, idxp);
    proj_kernel<<<dim3(128, 3), 256>>>(x, Wq, Wk, Wv, bq, bk, bv);
    attn_kernel<<<dim3(32, 4), 256, ATTN_SMEM>>>(gate, out);
    mem_kernel<<<dim3(64, 4), 128, MEM_SMEM>>>(mem_vals, gate, out);
}

// round 13
// speedup vs baseline: 1.1021x; 1.0042x over previous
#include <cuda_runtime.h>
#include <cstdint>

#define NB   4
#define TQ   2048
#define NE   1024
#define HD   128
#define TKF  4096
#define NM   16384

typedef unsigned long long ull;

// ---------------- packed f32x2 helpers (sm_103a only) ----------------
__device__ __forceinline__ ull dup2(float x) {
    ull r; asm("mov.b64 %0, {%1, %1};" : "=l"(r) : "f"(x)); return r;
}
__device__ __forceinline__ float2 u2f(ull v) {
    float2 r; asm("mov.b64 {%0, %1}, %2;" : "=f"(r.x), "=f"(r.y) : "l"(v)); return r;
}
__device__ __forceinline__ ull ffma2(ull a, ull b, ull c) {
    ull d; asm("fma.rn.f32x2 %0, %1, %2, %3;" : "=l"(d) : "l"(a), "l"(b), "l"(c)); return d;
}
__device__ __forceinline__ ull fmul2(ull a, ull b) {
    ull d; asm("mul.rn.f32x2 %0, %1, %2;" : "=l"(d) : "l"(a), "l"(b)); return d;
}

// ---------------- cp.async helpers ----------------
__device__ __forceinline__ void cp16(uint32_t dst_smem, const void* src) {
    asm volatile("cp.async.ca.shared.global [%0], [%1], 16;"
                 :: "r"(dst_smem), "l"(src));
}
__device__ __forceinline__ void cp_commit() {
    asm volatile("cp.async.commit_group;");
}
__device__ __forceinline__ void cp_wait0() {
    asm volatile("cp.async.wait_group 0;");
}

// ---------------- device scratch ----------------
__device__ float g_q [(size_t)NB * TQ  * HD];
__device__ float g_kf[(size_t)NB * TKF * HD];
__device__ float g_vf[(size_t)NB * TKF * HD];
// key-pair-interleaved copy of mem_keys
__device__ float g_ki[(size_t)NB * NM * HD];
// attention split-K partials: [half][b][q]
__device__ float g_am[(size_t)2 * NB * TQ];
__device__ float g_al[(size_t)2 * NB * TQ];
__device__ float g_ao[(size_t)2 * NB * TQ * HD];

// =========================================================================
// 0) key interleave pre-pass: pack key pairs along dims
// =========================================================================
__global__ __launch_bounds__(256) void interleave_kernel(
    const float* __restrict__ mem_keys)
{
    const int f4 = blockIdx.x * 256 + threadIdx.x;
    const int d2 = f4 & 63;
    const int p  = (f4 >> 6) & 8191;
    const int b  = f4 >> 19;
    const float2* r0 = (const float2*)(mem_keys + ((size_t)b * NM + 2 * p)     * HD) + d2;
    const float2* r1 = (const float2*)(mem_keys + ((size_t)b * NM + 2 * p + 1) * HD) + d2;
    float2 a = *r0, c = *r1;
    ((float4*)g_ki)[f4] = make_float4(a.x, c.x, a.y, c.y);
}

// =========================================================================
// 1) prefix copy
// =========================================================================
__global__ __launch_bounds__(256) void copy_prefix_kernel(
    const float* __restrict__ ki, const float* __restrict__ vi,
    const int* __restrict__ idxp)
{
    const int s  = idxp[0] * HD;
    const int e4 = blockIdx.x * 256 + threadIdx.x;
    const int d4 = e4 & 31;
    const int t  = (e4 >> 5) & (TQ - 1);
    const int b  = e4 >> 16;
    const size_t src = ((size_t)b * TQ + t) * NE + s + (size_t)d4 * 4;
    const size_t dst = ((size_t)b * TKF + t) * HD + (size_t)d4 * 4;
    *(float4*)(g_kf + dst) = *(const float4*)(ki + src);
    *(float4*)(g_vf + dst) = *(const float4*)(vi + src);
}

// =========================================================================
// 2) fused projection GEMM (packed FFMA2) — unchanged
// =========================================================================
__global__ __launch_bounds__(256) void proj_kernel(
    const float* __restrict__ X,
    const float* __restrict__ Wq, const float* __restrict__ Wk,
    const float* __restrict__ Wv,
    const float* __restrict__ bq, const float* __restrict__ bk,
    const float* __restrict__ bv)
{
    __shared__ float As[64][17];
    __shared__ float Bs[16][128];
    const int mode = blockIdx.y;
    const float* W    = (mode == 0) ? Wq : (mode == 1) ? Wk : Wv;
    const float* bias = (mode == 0) ? bq : (mode == 1) ? bk : bv;
    float* dst        = (mode == 0) ? g_q : (mode == 1) ? g_kf : g_vf;

    const int t   = threadIdx.x;
    const int bm0 = blockIdx.x * 64;
    const int tr  = t >> 4;
    const int tc  = t & 15;

    ull acc[4][4];
    #pragma unroll
    for (int i = 0; i < 4; i++)
        #pragma unroll
        for (int j = 0; j < 4; j++) acc[i][j] = 0ULL;

    const int ar = t >> 2, ac = (t & 3) * 4;
    const int br = t >> 5, bc = (t & 31) * 4;

    for (int k0 = 0; k0 < NE; k0 += 16) {
        float4 av = *(const float4*)(X + (size_t)(bm0 + ar) * NE + k0 + ac);
        As[ar][ac + 0] = av.x; As[ar][ac + 1] = av.y;
        As[ar][ac + 2] = av.z; As[ar][ac + 3] = av.w;
        *(float4*)(&Bs[br][bc])     = *(const float4*)(W + (size_t)(k0 + br) * HD + bc);
        *(float4*)(&Bs[br + 8][bc]) = *(const float4*)(W + (size_t)(k0 + br + 8) * HD + bc);
        __syncthreads();
        #pragma unroll
        for (int kk = 0; kk < 16; kk++) {
            ull pa[4];
            #pragma unroll
            for (int i = 0; i < 4; i++) pa[i] = dup2(As[tr * 4 + i][kk]);
            ulonglong2 b01 = *(const ulonglong2*)(&Bs[kk][tc * 8]);
            ulonglong2 b23 = *(const ulonglong2*)(&Bs[kk][tc * 8 + 4]);
            #pragma unroll
            for (int i = 0; i < 4; i++) {
                acc[i][0] = ffma2(pa[i], b01.x, acc[i][0]);
                acc[i][1] = ffma2(pa[i], b01.y, acc[i][1]);
                acc[i][2] = ffma2(pa[i], b23.x, acc[i][2]);
                acc[i][3] = ffma2(pa[i], b23.y, acc[i][3]);
            }
        }
        __syncthreads();
    }

    float4 bb0 = *(const float4*)(bias + tc * 8);
    float4 bb1 = *(const float4*)(bias + tc * 8 + 4);
    #pragma unroll
    for (int i = 0; i < 4; i++) {
        int row = bm0 + tr * 4 + i;
        int bi  = row >> 11;
        int tt  = row & (TQ - 1);
        size_t orow = (mode == 0) ? (size_t)row : ((size_t)bi * TKF + TQ + tt);
        float2 a0 = u2f(acc[i][0]), a1 = u2f(acc[i][1]);
        float2 a2 = u2f(acc[i][2]), a3 = u2f(acc[i][3]);
        float4 o0 = make_float4(a0.x + bb0.x, a0.y + bb0.y, a1.x + bb0.z, a1.y + bb0.w);
        float4 o1 = make_float4(a2.x + bb1.x, a2.y + bb1.y, a3.x + bb1.z, a3.y + bb1.w);
        *(float4*)(dst + orow * HD + tc * 8)     = o0;
        *(float4*)(dst + orow * HD + tc * 8 + 4) = o1;
    }
}

// =========================================================================
// 3) causal flash attention — split-K (z=2), single-buffered K/V,
//    2-stage PV staging (Ss 64x36). Writes partial (m, l, acc).
//    QK/softmax/PV arithmetic identical to R12 per key order.
// =========================================================================
// smem: Q 32KB | K 32KB | V 32KB | Ss 64*36*4 = 9216  -> 107520 B
#define ATTN_SMEM (3 * 32768 + 64 * 36 * 4)

__global__ __launch_bounds__(256, 2) void attn_kernel()
{
    extern __shared__ float smem_dyn[];
    float4* Qs = (float4*)smem_dyn;
    float4* Ks = Qs + 64 * 32;
    float4* Vs = Ks + 64 * 32;
    float*  Ss = (float*)(Vs + 64 * 32);      // 64 x 36

    const int t  = threadIdx.x;
    const int b  = blockIdx.y;
    const int qb = blockIdx.x;
    const int z  = blockIdx.z;                // key-range half
    const int tq = t >> 4;
    const int tk = t & 15;
    const float scale = 0.08838834764831845f;

    const float4* qsrc = (const float4*)(g_q + ((size_t)(b * TQ + qb * 64)) * HD);
    #pragma unroll
    for (int i = 0; i < 8; i++) {
        int idx = t + i * 256; int r = idx >> 5, c = idx & 31;
        Qs[r * 32 + (c ^ ((r >> 2) & 7))] = qsrc[idx];
    }

    float m[4], l[4];
    ull ac2[4][4];
    #pragma unroll
    for (int i = 0; i < 4; i++) {
        m[i] = -1e30f; l[i] = 0.f;
        #pragma unroll
        for (int j = 0; j < 4; j++) ac2[i][j] = 0ULL;
    }

    const float4* kbase = (const float4*)(g_kf + ((size_t)b * TKF) * HD);
    const float4* vbase = (const float4*)(g_vf + ((size_t)b * TKF) * HD);
    const int nt   = qb + 33;
    const int mid  = (nt + 1) >> 1;
    const int t0   = z ? mid : 0;
    const int tend = z ? nt : mid;

    for (int tile = t0; tile < tend; tile++) {
        __syncthreads();
        {
            uint32_t kd = (uint32_t)__cvta_generic_to_shared(Ks);
            uint32_t vd = (uint32_t)__cvta_generic_to_shared(Vs);
            const float4* ks = kbase + (size_t)tile * 2048;
            const float4* vs = vbase + (size_t)tile * 2048;
            #pragma unroll
            for (int i = 0; i < 8; i++) {
                int idx = t + i * 256; int r = idx >> 5, c = idx & 31;
                uint32_t off = (uint32_t)(r * 32 + (c ^ ((r >> 2) & 7))) * 16u;
                cp16(kd + off, ks + idx);
                cp16(vd + off, vs + idx);
            }
            cp_commit(); cp_wait0();
        }
        __syncthreads();

        // ---- QK^T (packed, identical) ----
        ull s2[4][4];
        #pragma unroll
        for (int i = 0; i < 4; i++)
            #pragma unroll
            for (int j = 0; j < 4; j++) s2[i][j] = 0ULL;

        #pragma unroll 4
        for (int c = 0; c < 32; c++) {
            ulonglong2 a2[4], k2[4];
            #pragma unroll
            for (int i = 0; i < 4; i++)
                a2[i] = *(const ulonglong2*)&Qs[(4 * tq + i) * 32 + (c ^ (tq & 7))];
            #pragma unroll
            for (int j = 0; j < 4; j++)
                k2[j] = *(const ulonglong2*)&Ks[(4 * tk + j) * 32 + (c ^ (tk & 7))];
            #pragma unroll
            for (int i = 0; i < 4; i++)
                #pragma unroll
                for (int j = 0; j < 4; j++)
                    s2[i][j] = ffma2(a2[i].x, k2[j].x,
                               ffma2(a2[i].y, k2[j].y, s2[i][j]));
        }

        float s[4][4];
        const bool lastTile = (tile == nt - 1);
        #pragma unroll
        for (int i = 0; i < 4; i++)
            #pragma unroll
            for (int j = 0; j < 4; j++) {
                float2 p = u2f(s2[i][j]);
                s[i][j] = (p.x + p.y) * scale;
                if (lastTile && (4 * tk + j > 4 * tq + i)) s[i][j] = -1e30f;
            }

        // ---- online softmax (identical) ----
        float tmax[4];
        #pragma unroll
        for (int i = 0; i < 4; i++)
            tmax[i] = fmaxf(fmaxf(s[i][0], s[i][1]), fmaxf(s[i][2], s[i][3]));
        #pragma unroll
        for (int o = 1; o < 16; o <<= 1)
            #pragma unroll
            for (int i = 0; i < 4; i++)
                tmax[i] = fmaxf(tmax[i], __shfl_xor_sync(0xffffffffu, tmax[i], o));

        float corr[4], rs[4];
        #pragma unroll
        for (int i = 0; i < 4; i++) {
            float mn = fmaxf(m[i], tmax[i]);
            corr[i] = __expf(m[i] - mn);
            m[i] = mn;
            rs[i] = 0.f;
            #pragma unroll
            for (int j = 0; j < 4; j++) {
                s[i][j] = __expf(s[i][j] - mn);
                rs[i] += s[i][j];
            }
        }
        #pragma unroll
        for (int o = 1; o < 16; o <<= 1)
            #pragma unroll
            for (int i = 0; i < 4; i++)
                rs[i] += __shfl_xor_sync(0xffffffffu, rs[i], o);
        #pragma unroll
        for (int i = 0; i < 4; i++) {
            l[i] = l[i] * corr[i] + rs[i];
            ull c2 = dup2(corr[i]);
            #pragma unroll
            for (int j = 0; j < 4; j++) ac2[i][j] = fmul2(ac2[i][j], c2);
        }

        // ---- P @ V in two 32-key stages (same ascending key order) ----
        #pragma unroll
        for (int stage = 0; stage < 2; stage++) {
            __syncthreads();
            if ((tk >> 3) == stage) {
                #pragma unroll
                for (int i = 0; i < 4; i++)
                    *(float4*)&Ss[(4 * tq + i) * 36 + 4 * (tk & 7)] =
                        make_float4(s[i][0], s[i][1], s[i][2], s[i][3]);
            }
            __syncthreads();

            #pragma unroll 2
            for (int jj = 0; jj < 8; jj++) {
                float4 p[4];
                #pragma unroll
                for (int i = 0; i < 4; i++)
                    p[i] = *(const float4*)&Ss[(4 * tq + i) * 36 + jj * 4];
                #pragma unroll
                for (int e = 0; e < 4; e++) {
                    int j = stage * 32 + jj * 4 + e;
                    int key = (j >> 2) & 7;
                    ulonglong2 v0 = *(const ulonglong2*)&Vs[j * 32 + (tk ^ key)];
                    ulonglong2 v1 = *(const ulonglong2*)&Vs[j * 32 + ((16 + tk) ^ key)];
                    #pragma unroll
                    for (int i = 0; i < 4; i++) {
                        float pv = (e == 0) ? p[i].x : (e == 1) ? p[i].y
                                 : (e == 2) ? p[i].z : p[i].w;
                        ull pv2 = dup2(pv);
                        ac2[i][0] = ffma2(pv2, v0.x, ac2[i][0]);
                        ac2[i][1] = ffma2(pv2, v0.y, ac2[i][1]);
                        ac2[i][2] = ffma2(pv2, v1.x, ac2[i][2]);
                        ac2[i][3] = ffma2(pv2, v1.y, ac2[i][3]);
                    }
                }
            }
        }
    }

    // ---- write partials (unnormalized) ----
    #pragma unroll
    for (int i = 0; i < 4; i++) {
        size_t prow = ((size_t)z * NB + b) * TQ + qb * 64 + 4 * tq + i;
        float2 a0 = u2f(ac2[i][0]), a1 = u2f(ac2[i][1]);
        float2 a2 = u2f(ac2[i][2]), a3 = u2f(ac2[i][3]);
        *(float4*)(g_ao + prow * HD + 4 * tk)      = make_float4(a0.x, a0.y, a1.x, a1.y);
        *(float4*)(g_ao + prow * HD + 64 + 4 * tk) = make_float4(a2.x, a2.y, a3.x, a3.y);
        if (tk == 0) { g_am[prow] = m[i]; g_al[prow] = l[i]; }
    }
}

// =========================================================================
// 3b) attention partial merge: combine 2 softmax partials, apply gate
// =========================================================================
__global__ __launch_bounds__(256) void attn_merge_kernel(
    const float* __restrict__ gate, float* __restrict__ out)
{
    const int idx = blockIdx.x * 256 + threadIdx.x;   // f4 units over NB*TQ*32
    const int row = idx >> 5;                          // b*TQ + q
    const float m0 = g_am[row], m1 = g_am[NB * TQ + row];
    const float l0 = g_al[row], l1 = g_al[NB * TQ + row];
    const float M  = fmaxf(m0, m1);
    const float w0 = __expf(m0 - M), w1 = __expf(m1 - M);
    const float inv = gate[0] / (w0 * l0 + w1 * l1);
    float4 a0 = ((const float4*)g_ao)[idx];
    float4 a1 = ((const float4*)g_ao)[(size_t)NB * TQ * 32 + idx];
    float4 o;
    o.x = (w0 * a0.x + w1 * a1.x) * inv;
    o.y = (w0 * a0.y + w1 * a1.y) * inv;
    o.z = (w0 * a0.z + w1 * a1.z) * inv;
    o.w = (w0 * a0.w + w1 * a1.w) * inv;
    ((float4*)out)[idx] = o;
}

// =========================================================================
// 4) kNN memory attention (R12 passing version, byte-identical)
// =========================================================================
#define MEM_SMEM (81920)

__global__ __launch_bounds__(128, 2) void mem_kernel(
    const float* __restrict__ mem_vals,
    const float* __restrict__ gate, float* __restrict__ out)
{
    extern __shared__ float msm[];
    float4* Qs  = (float4*)msm;
    float4* Ks0 = (float4*)(msm + 4096);
    float4* Ks1 = (float4*)(msm + 12288);
    float*  lv_s = msm;
    int*    li_s = (int*)(msm + 4096);

    const int t    = threadIdx.x;
    const int b    = blockIdx.y;
    const int q0   = blockIdx.x * 32;
    const int tq   = t >> 3;
    const int g    = t & 7;
    const int h    = g >> 2;
    const int lane = t & 31;

    const float4* qsrc = (const float4*)(g_q + ((size_t)(b * TQ + q0)) * HD);
    #pragma unroll
    for (int i = 0; i < 8; i++) {
        int idx = t + i * 128; int r = idx >> 5, c = idx & 31;
        Qs[r * 32 + (c ^ (r & 7))] = qsrc[idx];
    }

    float lv[32]; int li[32];
    #pragma unroll
    for (int i = 0; i < 32; i++) { lv[i] = -1e30f; li[i] = 0; }
    float Tsh = -1e30f;

    const float4* kb = (const float4*)g_ki + (size_t)b * 8192 * 64;

    {
        uint32_t kd = (uint32_t)__cvta_generic_to_shared(Ks0);
        #pragma unroll
        for (int i = 0; i < 16; i++) {
            int idx = t + i * 128; int row = idx >> 6, col = idx & 63;
            uint32_t off = (uint32_t)(row * 64 + (col ^ (row >> 2))) * 16u;
            cp16(kd + off, kb + idx);
        }
        cp_commit();
    }

    for (int tile = 0; tile < NM / 64; tile++) {
        cp_wait0();
        __syncthreads();
        const float4* Ks = (tile & 1) ? Ks1 : Ks0;

        if (tile + 1 < NM / 64) {
            float4* Kn = (tile & 1) ? Ks0 : Ks1;
            uint32_t kd = (uint32_t)__cvta_generic_to_shared(Kn);
            const float4* ks = kb + (size_t)(tile + 1) * 2048;
            #pragma unroll
            for (int i = 0; i < 16; i++) {
                int idx = t + i * 128; int row = idx >> 6, col = idx & 63;
                uint32_t off = (uint32_t)(row * 64 + (col ^ (row >> 2))) * 16u;
                cp16(kd + off, ks + idx);
            }
            cp_commit();
        }

        ull acc[2][4];
        #pragma unroll
        for (int j = 0; j < 4; j++) { acc[0][j] = 0ULL; acc[1][j] = 0ULL; }

        #pragma unroll 4
        for (int c = 0; c < 32; c++) {
            float4 aA = Qs[tq * 32 + (c ^ (tq & 7))];
            float4 aB = Qs[(tq + 16) * 32 + (c ^ (tq & 7))];
            ull axA = dup2(aA.x), ayA = dup2(aA.y), azA = dup2(aA.z), awA = dup2(aA.w);
            ull axB = dup2(aB.x), ayB = dup2(aB.y), azB = dup2(aB.z), awB = dup2(aB.w);
            #pragma unroll
            for (int j = 0; j < 4; j++) {
                int row  = 4 * g + j;
                int base = row * 64;
                ulonglong2 k01 = *(const ulonglong2*)&Ks[base + ((2 * c)     ^ g)];
                ulonglong2 k23 = *(const ulonglong2*)&Ks[base + ((2 * c + 1) ^ g)];
                acc[0][j] = ffma2(axA, k01.x, acc[0][j]);
                acc[0][j] = ffma2(ayA, k01.y, acc[0][j]);
                acc[0][j] = ffma2(azA, k23.x, acc[0][j]);
                acc[0][j] = ffma2(awA, k23.y, acc[0][j]);
                acc[1][j] = ffma2(axB, k01.x, acc[1][j]);
                acc[1][j] = ffma2(ayB, k01.y, acc[1][j]);
                acc[1][j] = ffma2(azB, k23.x, acc[1][j]);
                acc[1][j] = ffma2(awB, k23.y, acc[1][j]);
            }
        }

        float sA[8], sB[8];
        #pragma unroll
        for (int j = 0; j < 4; j++) {
            float2 pa = u2f(acc[0][j]);
            float2 pb = u2f(acc[1][j]);
            sA[2 * j] = pa.x; sA[2 * j + 1] = pa.y;
            sB[2 * j] = pb.x; sB[2 * j + 1] = pb.y;
        }

        #pragma unroll
        for (int j = 0; j < 8; j++) {
            float rA = __shfl_xor_sync(0xffffffffu, sA[j], 4);
            float rB = __shfl_xor_sync(0xffffffffu, sB[j], 4);
            float c1 = h ? sB[j] : sA[j];
            float c2 = h ? rB : rA;
            int   i1 = tile * 64 + 8 * g + j;
            int   i2 = tile * 64 + 8 * (g ^ 4) + j;
            if (c1 > fmaxf(Tsh, lv[31])) {
                bool pp = true;
                #pragma unroll
                for (int p = 31; p >= 1; p--) {
                    bool pr = lv[p - 1] < c1;
                    float nv = pr ? lv[p - 1] : (pp ? c1 : lv[p]);
                    int   ni = pr ? li[p - 1] : (pp ? i1 : li[p]);
                    lv[p] = nv; li[p] = ni;
                    pp = pr;
                }
                if (pp) { lv[0] = c1; li[0] = i1; }
            }
            if (c2 > fmaxf(Tsh, lv[31])) {
                bool pp = true;
                #pragma unroll
                for (int p = 31; p >= 1; p--) {
                    bool pr = lv[p - 1] < c2;
                    float nv = pr ? lv[p - 1] : (pp ? c2 : lv[p]);
                    int   ni = pr ? li[p - 1] : (pp ? i2 : li[p]);
                    lv[p] = nv; li[p] = ni;
                    pp = pr;
                }
                if (pp) { lv[0] = c2; li[0] = i2; }
            }
        }
        {
            float tm = lv[31];
            tm = fmaxf(tm, __shfl_xor_sync(0xffffffffu, tm, 1));
            tm = fmaxf(tm, __shfl_xor_sync(0xffffffffu, tm, 2));
            Tsh = tm;
        }
        __syncthreads();
    }

    #pragma unroll
    for (int p = 0; p < 32; p++) {
        lv_s[p * 128 + t] = lv[p];
        li_s[p * 128 + t] = li[p];
    }
    __syncthreads();

    const float* vb = mem_vals + (size_t)b * NM * HD;
    const float scg = 1.0f - gate[0];

    #pragma unroll
    for (int pass = 0; pass < 2; pass++) {
        const bool mine = (h == pass);
        float accv[16];
        #pragma unroll
        for (int u = 0; u < 16; u++) accv[u] = 0.f;
        float sumw = 0.f, vmax = 0.f;
        int ptr = 0;

        for (int it = 0; it < 32; it++) {
            float bv = (mine && ptr < 32) ? lv_s[ptr * 128 + t] : -1e30f;
            int   wl = lane;
            #pragma unroll
            for (int o = 1; o < 8; o <<= 1) {
                float ov = __shfl_xor_sync(0xffffffffu, bv, o);
                int   ol = __shfl_xor_sync(0xffffffffu, wl, o);
                if (ov > bv) { bv = ov; wl = ol; }
            }
            int myi  = li_s[(ptr < 32 ? ptr : 31) * 128 + t];
            int widx = __shfl_sync(0xffffffffu, myi, wl);
            if (lane == wl) ptr++;
            if (it == 0) vmax = bv;
            float w = __expf((bv - vmax) * 0.03125f);
            sumw += w;
            const float4* vrow = (const float4*)(vb + (size_t)widx * HD) + g * 4;
            #pragma unroll
            for (int u = 0; u < 4; u++) {
                float4 vv = vrow[u];
                accv[4 * u + 0] = fmaf(w, vv.x, accv[4 * u + 0]);
                accv[4 * u + 1] = fmaf(w, vv.y, accv[4 * u + 1]);
                accv[4 * u + 2] = fmaf(w, vv.z, accv[4 * u + 2]);
                accv[4 * u + 3] = fmaf(w, vv.w, accv[4 * u + 3]);
            }
        }

        const float sc = scg / sumw;
        const int   qq = q0 + tq + (pass ? 16 : 0);
        float* orow = out + ((size_t)(b * TQ + qq)) * HD + g * 16;
        #pragma unroll
        for (int u = 0; u < 4; u++) {
            float4 o = ((float4*)orow)[u];
            o.x += sc * accv[4 * u + 0];
            o.y += sc * accv[4 * u + 1];
            o.z += sc * accv[4 * u + 2];
            o.w += sc * accv[4 * u + 3];
            ((float4*)orow)[u] = o;
        }
    }
}

// =========================================================================
extern "C" void kernel_launch(void* const* d_in, const int* in_sizes, int n_in,
                              void* d_out, int out_size) {
    const float* x        = (const float*)d_in[0];
    const float* ki       = (const float*)d_in[1];
    const float* vi       = (const float*)d_in[2];
    const float* mem_keys = (const float*)d_in[3];
    const float* mem_vals = (const float*)d_in[4];
    const float* Wq       = (const float*)d_in[5];
    const float* bq       = (const float*)d_in[6];
    const float* Wk       = (const float*)d_in[7];
    const float* bk       = (const float*)d_in[8];
    const float* Wv       = (const float*)d_in[9];
    const float* bv       = (const float*)d_in[10];
    const float* gate     = (const float*)d_in[11];
    const int*   idxp     = (const int*)d_in[12];
    float* out = (float*)d_out;

    cudaFuncSetAttribute(attn_kernel, cudaFuncAttributeMaxDynamicSharedMemorySize,
                         ATTN_SMEM);
    cudaFuncSetAttribute(mem_kernel, cudaFuncAttributeMaxDynamicSharedMemorySize,
                         MEM_SMEM);

    interleave_kernel<<<8192, 256>>>(mem_keys);
    copy_prefix_kernel<<<1024, 256>>>(ki, vi, idxp);
    proj_kernel<<<dim3(128, 3), 256>>>(x, Wq, Wk, Wv, bq, bk, bv);
    attn_kernel<<<dim3(32, 4, 2), 256, ATTN_SMEM>>>();
    attn_merge_kernel<<<1024, 256>>>(gate, out);
    mem_kernel<<<dim3(64, 4), 128, MEM_SMEM>>>(mem_vals, gate, out);
}

// round 14
// speedup vs baseline: 1.1505x; 1.0439x over previous
#include <cuda_runtime.h>
#include <cstdint>

#define NB   4
#define TQ   2048
#define NE   1024
#define HD   128
#define TKF  4096
#define NM   16384

typedef unsigned long long ull;

// ---------------- packed f32x2 helpers (sm_103a only) ----------------
__device__ __forceinline__ ull dup2(float x) {
    ull r; asm("mov.b64 %0, {%1, %1};" : "=l"(r) : "f"(x)); return r;
}
__device__ __forceinline__ float2 u2f(ull v) {
    float2 r; asm("mov.b64 {%0, %1}, %2;" : "=f"(r.x), "=f"(r.y) : "l"(v)); return r;
}
__device__ __forceinline__ ull ffma2(ull a, ull b, ull c) {
    ull d; asm("fma.rn.f32x2 %0, %1, %2, %3;" : "=l"(d) : "l"(a), "l"(b), "l"(c)); return d;
}
__device__ __forceinline__ ull fmul2(ull a, ull b) {
    ull d; asm("mul.rn.f32x2 %0, %1, %2;" : "=l"(d) : "l"(a), "l"(b)); return d;
}

// ---------------- cp.async helpers ----------------
__device__ __forceinline__ void cp16(uint32_t dst_smem, const void* src) {
    asm volatile("cp.async.ca.shared.global [%0], [%1], 16;"
                 :: "r"(dst_smem), "l"(src));
}
__device__ __forceinline__ void cp_commit() {
    asm volatile("cp.async.commit_group;");
}
__device__ __forceinline__ void cp_wait0() {
    asm volatile("cp.async.wait_group 0;");
}

// ---------------- device scratch ----------------
__device__ float g_q [(size_t)NB * TQ  * HD];
__device__ float g_kf[(size_t)NB * TKF * HD];
__device__ float g_vf[(size_t)NB * TKF * HD];
// key-pair-interleaved copy of mem_keys
__device__ float g_ki[(size_t)NB * NM * HD];
// attention split-K partials: [half][b][q]
__device__ float g_am[(size_t)2 * NB * TQ];
__device__ float g_al[(size_t)2 * NB * TQ];
__device__ float g_ao[(size_t)2 * NB * TQ * HD];

// =========================================================================
// 0) key interleave pre-pass: pack key pairs along dims
// =========================================================================
__global__ __launch_bounds__(256) void interleave_kernel(
    const float* __restrict__ mem_keys)
{
    const int f4 = blockIdx.x * 256 + threadIdx.x;
    const int d2 = f4 & 63;
    const int p  = (f4 >> 6) & 8191;
    const int b  = f4 >> 19;
    const float2* r0 = (const float2*)(mem_keys + ((size_t)b * NM + 2 * p)     * HD) + d2;
    const float2* r1 = (const float2*)(mem_keys + ((size_t)b * NM + 2 * p + 1) * HD) + d2;
    float2 a = *r0, c = *r1;
    ((float4*)g_ki)[f4] = make_float4(a.x, c.x, a.y, c.y);
}

// =========================================================================
// 1) prefix copy
// =========================================================================
__global__ __launch_bounds__(256) void copy_prefix_kernel(
    const float* __restrict__ ki, const float* __restrict__ vi,
    const int* __restrict__ idxp)
{
    const int s  = idxp[0] * HD;
    const int e4 = blockIdx.x * 256 + threadIdx.x;
    const int d4 = e4 & 31;
    const int t  = (e4 >> 5) & (TQ - 1);
    const int b  = e4 >> 16;
    const size_t src = ((size_t)b * TQ + t) * NE + s + (size_t)d4 * 4;
    const size_t dst = ((size_t)b * TKF + t) * HD + (size_t)d4 * 4;
    *(float4*)(g_kf + dst) = *(const float4*)(ki + src);
    *(float4*)(g_vf + dst) = *(const float4*)(vi + src);
}

// =========================================================================
// 2) fused projection GEMM (packed FFMA2) — unchanged
// =========================================================================
__global__ __launch_bounds__(256) void proj_kernel(
    const float* __restrict__ X,
    const float* __restrict__ Wq, const float* __restrict__ Wk,
    const float* __restrict__ Wv,
    const float* __restrict__ bq, const float* __restrict__ bk,
    const float* __restrict__ bv)
{
    __shared__ float As[64][17];
    __shared__ float Bs[16][128];
    const int mode = blockIdx.y;
    const float* W    = (mode == 0) ? Wq : (mode == 1) ? Wk : Wv;
    const float* bias = (mode == 0) ? bq : (mode == 1) ? bk : bv;
    float* dst        = (mode == 0) ? g_q : (mode == 1) ? g_kf : g_vf;

    const int t   = threadIdx.x;
    const int bm0 = blockIdx.x * 64;
    const int tr  = t >> 4;
    const int tc  = t & 15;

    ull acc[4][4];
    #pragma unroll
    for (int i = 0; i < 4; i++)
        #pragma unroll
        for (int j = 0; j < 4; j++) acc[i][j] = 0ULL;

    const int ar = t >> 2, ac = (t & 3) * 4;
    const int br = t >> 5, bc = (t & 31) * 4;

    for (int k0 = 0; k0 < NE; k0 += 16) {
        float4 av = *(const float4*)(X + (size_t)(bm0 + ar) * NE + k0 + ac);
        As[ar][ac + 0] = av.x; As[ar][ac + 1] = av.y;
        As[ar][ac + 2] = av.z; As[ar][ac + 3] = av.w;
        *(float4*)(&Bs[br][bc])     = *(const float4*)(W + (size_t)(k0 + br) * HD + bc);
        *(float4*)(&Bs[br + 8][bc]) = *(const float4*)(W + (size_t)(k0 + br + 8) * HD + bc);
        __syncthreads();
        #pragma unroll
        for (int kk = 0; kk < 16; kk++) {
            ull pa[4];
            #pragma unroll
            for (int i = 0; i < 4; i++) pa[i] = dup2(As[tr * 4 + i][kk]);
            ulonglong2 b01 = *(const ulonglong2*)(&Bs[kk][tc * 8]);
            ulonglong2 b23 = *(const ulonglong2*)(&Bs[kk][tc * 8 + 4]);
            #pragma unroll
            for (int i = 0; i < 4; i++) {
                acc[i][0] = ffma2(pa[i], b01.x, acc[i][0]);
                acc[i][1] = ffma2(pa[i], b01.y, acc[i][1]);
                acc[i][2] = ffma2(pa[i], b23.x, acc[i][2]);
                acc[i][3] = ffma2(pa[i], b23.y, acc[i][3]);
            }
        }
        __syncthreads();
    }

    float4 bb0 = *(const float4*)(bias + tc * 8);
    float4 bb1 = *(const float4*)(bias + tc * 8 + 4);
    #pragma unroll
    for (int i = 0; i < 4; i++) {
        int row = bm0 + tr * 4 + i;
        int bi  = row >> 11;
        int tt  = row & (TQ - 1);
        size_t orow = (mode == 0) ? (size_t)row : ((size_t)bi * TKF + TQ + tt);
        float2 a0 = u2f(acc[i][0]), a1 = u2f(acc[i][1]);
        float2 a2 = u2f(acc[i][2]), a3 = u2f(acc[i][3]);
        float4 o0 = make_float4(a0.x + bb0.x, a0.y + bb0.y, a1.x + bb0.z, a1.y + bb0.w);
        float4 o1 = make_float4(a2.x + bb1.x, a2.y + bb1.y, a3.x + bb1.z, a3.y + bb1.w);
        *(float4*)(dst + orow * HD + tc * 8)     = o0;
        *(float4*)(dst + orow * HD + tc * 8 + 4) = o1;
    }
}

// =========================================================================
// 3) causal flash attention — split-K (z=2), unchanged from R13 passing
// =========================================================================
#define ATTN_SMEM (3 * 32768 + 64 * 36 * 4)

__global__ __launch_bounds__(256, 2) void attn_kernel()
{
    extern __shared__ float smem_dyn[];
    float4* Qs = (float4*)smem_dyn;
    float4* Ks = Qs + 64 * 32;
    float4* Vs = Ks + 64 * 32;
    float*  Ss = (float*)(Vs + 64 * 32);

    const int t  = threadIdx.x;
    const int b  = blockIdx.y;
    const int qb = blockIdx.x;
    const int z  = blockIdx.z;
    const int tq = t >> 4;
    const int tk = t & 15;
    const float scale = 0.08838834764831845f;

    const float4* qsrc = (const float4*)(g_q + ((size_t)(b * TQ + qb * 64)) * HD);
    #pragma unroll
    for (int i = 0; i < 8; i++) {
        int idx = t + i * 256; int r = idx >> 5, c = idx & 31;
        Qs[r * 32 + (c ^ ((r >> 2) & 7))] = qsrc[idx];
    }

    float m[4], l[4];
    ull ac2[4][4];
    #pragma unroll
    for (int i = 0; i < 4; i++) {
        m[i] = -1e30f; l[i] = 0.f;
        #pragma unroll
        for (int j = 0; j < 4; j++) ac2[i][j] = 0ULL;
    }

    const float4* kbase = (const float4*)(g_kf + ((size_t)b * TKF) * HD);
    const float4* vbase = (const float4*)(g_vf + ((size_t)b * TKF) * HD);
    const int nt   = qb + 33;
    const int mid  = (nt + 1) >> 1;
    const int t0   = z ? mid : 0;
    const int tend = z ? nt : mid;

    for (int tile = t0; tile < tend; tile++) {
        __syncthreads();
        {
            uint32_t kd = (uint32_t)__cvta_generic_to_shared(Ks);
            uint32_t vd = (uint32_t)__cvta_generic_to_shared(Vs);
            const float4* ks = kbase + (size_t)tile * 2048;
            const float4* vs = vbase + (size_t)tile * 2048;
            #pragma unroll
            for (int i = 0; i < 8; i++) {
                int idx = t + i * 256; int r = idx >> 5, c = idx & 31;
                uint32_t off = (uint32_t)(r * 32 + (c ^ ((r >> 2) & 7))) * 16u;
                cp16(kd + off, ks + idx);
                cp16(vd + off, vs + idx);
            }
            cp_commit(); cp_wait0();
        }
        __syncthreads();

        ull s2[4][4];
        #pragma unroll
        for (int i = 0; i < 4; i++)
            #pragma unroll
            for (int j = 0; j < 4; j++) s2[i][j] = 0ULL;

        #pragma unroll 4
        for (int c = 0; c < 32; c++) {
            ulonglong2 a2[4], k2[4];
            #pragma unroll
            for (int i = 0; i < 4; i++)
                a2[i] = *(const ulonglong2*)&Qs[(4 * tq + i) * 32 + (c ^ (tq & 7))];
            #pragma unroll
            for (int j = 0; j < 4; j++)
                k2[j] = *(const ulonglong2*)&Ks[(4 * tk + j) * 32 + (c ^ (tk & 7))];
            #pragma unroll
            for (int i = 0; i < 4; i++)
                #pragma unroll
                for (int j = 0; j < 4; j++)
                    s2[i][j] = ffma2(a2[i].x, k2[j].x,
                               ffma2(a2[i].y, k2[j].y, s2[i][j]));
        }

        float s[4][4];
        const bool lastTile = (tile == nt - 1);
        #pragma unroll
        for (int i = 0; i < 4; i++)
            #pragma unroll
            for (int j = 0; j < 4; j++) {
                float2 p = u2f(s2[i][j]);
                s[i][j] = (p.x + p.y) * scale;
                if (lastTile && (4 * tk + j > 4 * tq + i)) s[i][j] = -1e30f;
            }

        float tmax[4];
        #pragma unroll
        for (int i = 0; i < 4; i++)
            tmax[i] = fmaxf(fmaxf(s[i][0], s[i][1]), fmaxf(s[i][2], s[i][3]));
        #pragma unroll
        for (int o = 1; o < 16; o <<= 1)
            #pragma unroll
            for (int i = 0; i < 4; i++)
                tmax[i] = fmaxf(tmax[i], __shfl_xor_sync(0xffffffffu, tmax[i], o));

        float corr[4], rs[4];
        #pragma unroll
        for (int i = 0; i < 4; i++) {
            float mn = fmaxf(m[i], tmax[i]);
            corr[i] = __expf(m[i] - mn);
            m[i] = mn;
            rs[i] = 0.f;
            #pragma unroll
            for (int j = 0; j < 4; j++) {
                s[i][j] = __expf(s[i][j] - mn);
                rs[i] += s[i][j];
            }
        }
        #pragma unroll
        for (int o = 1; o < 16; o <<= 1)
            #pragma unroll
            for (int i = 0; i < 4; i++)
                rs[i] += __shfl_xor_sync(0xffffffffu, rs[i], o);
        #pragma unroll
        for (int i = 0; i < 4; i++) {
            l[i] = l[i] * corr[i] + rs[i];
            ull c2 = dup2(corr[i]);
            #pragma unroll
            for (int j = 0; j < 4; j++) ac2[i][j] = fmul2(ac2[i][j], c2);
        }

        #pragma unroll
        for (int stage = 0; stage < 2; stage++) {
            __syncthreads();
            if ((tk >> 3) == stage) {
                #pragma unroll
                for (int i = 0; i < 4; i++)
                    *(float4*)&Ss[(4 * tq + i) * 36 + 4 * (tk & 7)] =
                        make_float4(s[i][0], s[i][1], s[i][2], s[i][3]);
            }
            __syncthreads();

            #pragma unroll 2
            for (int jj = 0; jj < 8; jj++) {
                float4 p[4];
                #pragma unroll
                for (int i = 0; i < 4; i++)
                    p[i] = *(const float4*)&Ss[(4 * tq + i) * 36 + jj * 4];
                #pragma unroll
                for (int e = 0; e < 4; e++) {
                    int j = stage * 32 + jj * 4 + e;
                    int key = (j >> 2) & 7;
                    ulonglong2 v0 = *(const ulonglong2*)&Vs[j * 32 + (tk ^ key)];
                    ulonglong2 v1 = *(const ulonglong2*)&Vs[j * 32 + ((16 + tk) ^ key)];
                    #pragma unroll
                    for (int i = 0; i < 4; i++) {
                        float pv = (e == 0) ? p[i].x : (e == 1) ? p[i].y
                                 : (e == 2) ? p[i].z : p[i].w;
                        ull pv2 = dup2(pv);
                        ac2[i][0] = ffma2(pv2, v0.x, ac2[i][0]);
                        ac2[i][1] = ffma2(pv2, v0.y, ac2[i][1]);
                        ac2[i][2] = ffma2(pv2, v1.x, ac2[i][2]);
                        ac2[i][3] = ffma2(pv2, v1.y, ac2[i][3]);
                    }
                }
            }
        }
    }

    #pragma unroll
    for (int i = 0; i < 4; i++) {
        size_t prow = ((size_t)z * NB + b) * TQ + qb * 64 + 4 * tq + i;
        float2 a0 = u2f(ac2[i][0]), a1 = u2f(ac2[i][1]);
        float2 a2 = u2f(ac2[i][2]), a3 = u2f(ac2[i][3]);
        *(float4*)(g_ao + prow * HD + 4 * tk)      = make_float4(a0.x, a0.y, a1.x, a1.y);
        *(float4*)(g_ao + prow * HD + 64 + 4 * tk) = make_float4(a2.x, a2.y, a3.x, a3.y);
        if (tk == 0) { g_am[prow] = m[i]; g_al[prow] = l[i]; }
    }
}

// =========================================================================
// 3b) attention partial merge (unchanged from R13)
// =========================================================================
__global__ __launch_bounds__(256) void attn_merge_kernel(
    const float* __restrict__ gate, float* __restrict__ out)
{
    const int idx = blockIdx.x * 256 + threadIdx.x;
    const int row = idx >> 5;
    const float m0 = g_am[row], m1 = g_am[NB * TQ + row];
    const float l0 = g_al[row], l1 = g_al[NB * TQ + row];
    const float M  = fmaxf(m0, m1);
    const float w0 = __expf(m0 - M), w1 = __expf(m1 - M);
    const float inv = gate[0] / (w0 * l0 + w1 * l1);
    float4 a0 = ((const float4*)g_ao)[idx];
    float4 a1 = ((const float4*)g_ao)[(size_t)NB * TQ * 32 + idx];
    float4 o;
    o.x = (w0 * a0.x + w1 * a1.x) * inv;
    o.y = (w0 * a0.y + w1 * a1.y) * inv;
    o.z = (w0 * a0.z + w1 * a1.z) * inv;
    o.w = (w0 * a0.w + w1 * a1.w) * inv;
    ((float4*)out)[idx] = o;
}

// =========================================================================
// 4) kNN memory attention v5: 4 queries x 4 keys per thread.
//    Per-key score chains bit-identical (packed key pairs, dims in order).
//    Owner routing via intra-16-lane shfl; 4-pass merge.
// =========================================================================
#define MEM_SMEM (81920)

__global__ __launch_bounds__(128, 2) void mem_kernel(
    const float* __restrict__ mem_vals,
    const float* __restrict__ gate, float* __restrict__ out)
{
    extern __shared__ float msm[];
    float4* Qs  = (float4*)msm;                   // [0, 16KB)
    float4* Ks0 = (float4*)(msm + 4096);          // [16KB, 48KB)
    float4* Ks1 = (float4*)(msm + 12288);         // [48KB, 80KB)
    float*  lv_s = msm;                           // overlay [0, 16KB)
    int*    li_s = (int*)(msm + 4096);            // overlay [16KB, 32KB)

    const int t    = threadIdx.x;                 // 0..127
    const int b    = blockIdx.y;
    const int q0   = blockIdx.x * 32;
    const int tq2  = t >> 4;                      // 0..7 -> queries 4*tq2..+3
    const int g    = t & 15;                      // pair rows 2g,2g+1 (keys 4g..4g+3)
    const int o    = g >> 2;                      // owned query slot (0..3)
    const int sk   = g & 7;                       // K swizzle key
    const int lane = t & 31;

    const float4* qsrc = (const float4*)(g_q + ((size_t)(b * TQ + q0)) * HD);
    #pragma unroll
    for (int i = 0; i < 8; i++) {
        int idx = t + i * 128; int r = idx >> 5, c = idx & 31;
        Qs[r * 32 + (c ^ (r & 7))] = qsrc[idx];
    }

    float lv[32]; int li[32];
    #pragma unroll
    for (int i = 0; i < 32; i++) { lv[i] = -1e30f; li[i] = 0; }
    float Tsh = -1e30f;

    const float4* kb = (const float4*)g_ki + (size_t)b * 8192 * 64;

    // prefetch tile 0 (swizzle key = (row>>1)&7)
    {
        uint32_t kd = (uint32_t)__cvta_generic_to_shared(Ks0);
        #pragma unroll
        for (int i = 0; i < 16; i++) {
            int idx = t + i * 128; int row = idx >> 6, col = idx & 63;
            uint32_t off = (uint32_t)(row * 64 + (col ^ ((row >> 1) & 7))) * 16u;
            cp16(kd + off, kb + idx);
        }
        cp_commit();
    }

    for (int tile = 0; tile < NM / 64; tile++) {
        cp_wait0();
        __syncthreads();
        const float4* Ks = (tile & 1) ? Ks1 : Ks0;

        if (tile + 1 < NM / 64) {
            float4* Kn = (tile & 1) ? Ks0 : Ks1;
            uint32_t kd = (uint32_t)__cvta_generic_to_shared(Kn);
            const float4* ks = kb + (size_t)(tile + 1) * 2048;
            #pragma unroll
            for (int i = 0; i < 16; i++) {
                int idx = t + i * 128; int row = idx >> 6, col = idx & 63;
                uint32_t off = (uint32_t)(row * 64 + (col ^ ((row >> 1) & 7))) * 16u;
                cp16(kd + off, ks + idx);
            }
            cp_commit();
        }

        // ---- scores: 4 queries x 2 pairs; per-key chains bit-identical ----
        ull acc[4][2];
        #pragma unroll
        for (int i = 0; i < 4; i++) { acc[i][0] = 0ULL; acc[i][1] = 0ULL; }

        #pragma unroll 4
        for (int c = 0; c < 32; c++) {
            ull ax[4], ay[4], az[4], aw[4];
            #pragma unroll
            for (int i = 0; i < 4; i++) {
                int q = 4 * tq2 + i;
                float4 a = Qs[q * 32 + (c ^ (q & 7))];
                ax[i] = dup2(a.x); ay[i] = dup2(a.y);
                az[i] = dup2(a.z); aw[i] = dup2(a.w);
            }
            #pragma unroll
            for (int jj = 0; jj < 2; jj++) {
                int base = (2 * g + jj) * 64;
                ulonglong2 k01 = *(const ulonglong2*)&Ks[base + ((2 * c)     ^ sk)];
                ulonglong2 k23 = *(const ulonglong2*)&Ks[base + ((2 * c + 1) ^ sk)];
                #pragma unroll
                for (int i = 0; i < 4; i++) {
                    acc[i][jj] = ffma2(ax[i], k01.x, acc[i][jj]);
                    acc[i][jj] = ffma2(ay[i], k01.y, acc[i][jj]);
                    acc[i][jj] = ffma2(az[i], k23.x, acc[i][jj]);
                    acc[i][jj] = ffma2(aw[i], k23.y, acc[i][jj]);
                }
            }
        }

        float s[4][4];
        #pragma unroll
        for (int i = 0; i < 4; i++) {
            float2 p0 = u2f(acc[i][0]);
            float2 p1 = u2f(acc[i][1]);
            s[i][0] = p0.x; s[i][1] = p0.y;
            s[i][2] = p1.x; s[i][3] = p1.y;
        }

        // ---- route scores to owner lanes and insert ----
        #pragma unroll
        for (int r = 0; r < 4; r++) {
            const int qs  = o ^ r;                    // query slot I send
            const int src = g ^ (r << 2);             // lane whose keys I receive
            const int kb0 = tile * 64 + 4 * src;
            #pragma unroll
            for (int j = 0; j < 4; j++) {
                float cv = (r == 0) ? s[o][j]
                         : __shfl_xor_sync(0xffffffffu, s[qs][j], r << 2);
                if (cv > fmaxf(Tsh, lv[31])) {
                    int kidx = kb0 + j;
                    bool pp = true;
                    #pragma unroll
                    for (int p = 31; p >= 1; p--) {
                        bool pr = lv[p - 1] < cv;
                        float nv = pr ? lv[p - 1] : (pp ? cv : lv[p]);
                        int   ni = pr ? li[p - 1] : (pp ? kidx : li[p]);
                        lv[p] = nv; li[p] = ni;
                        pp = pr;
                    }
                    if (pp) { lv[0] = cv; li[0] = kidx; }
                }
            }
        }
        // threshold over the 4 lanes owning the SAME query (masks 1,2)
        {
            float tm = lv[31];
            tm = fmaxf(tm, __shfl_xor_sync(0xffffffffu, tm, 1));
            tm = fmaxf(tm, __shfl_xor_sync(0xffffffffu, tm, 2));
            Tsh = tm;
        }
        __syncthreads();
    }

    // ---- dump sorted lists to smem (tiles/Q dead) ----
    #pragma unroll
    for (int p = 0; p < 32; p++) {
        lv_s[p * 128 + t] = lv[p];
        li_s[p * 128 + t] = li[p];
    }
    __syncthreads();

    // ---- 4 merge passes: pass p = query 4*tq2+p ----
    const float* vb = mem_vals + (size_t)b * NM * HD;
    const float scg = 1.0f - gate[0];

    for (int pass = 0; pass < 4; pass++) {
        const bool mine = (o == pass);
        float accv[8];
        #pragma unroll
        for (int u = 0; u < 8; u++) accv[u] = 0.f;
        float sumw = 0.f, vmax = 0.f;
        int ptr = 0;

        for (int it = 0; it < 32; it++) {
            float bv = (mine && ptr < 32) ? lv_s[ptr * 128 + t] : -1e30f;
            int   wl = lane;
            #pragma unroll
            for (int off = 1; off < 16; off <<= 1) {
                float ov = __shfl_xor_sync(0xffffffffu, bv, off);
                int   ol = __shfl_xor_sync(0xffffffffu, wl, off);
                if (ov > bv) { bv = ov; wl = ol; }
            }
            int myi  = li_s[(ptr < 32 ? ptr : 31) * 128 + t];
            int widx = __shfl_sync(0xffffffffu, myi, wl);
            if (lane == wl) ptr++;
            if (it == 0) vmax = bv;
            float w = __expf((bv - vmax) * 0.03125f);   // 1/sqrt(1024)
            sumw += w;
            const float4* vrow = (const float4*)(vb + (size_t)widx * HD) + g * 2;
            #pragma unroll
            for (int u = 0; u < 2; u++) {
                float4 vv = vrow[u];
                accv[4 * u + 0] = fmaf(w, vv.x, accv[4 * u + 0]);
                accv[4 * u + 1] = fmaf(w, vv.y, accv[4 * u + 1]);
                accv[4 * u + 2] = fmaf(w, vv.z, accv[4 * u + 2]);
                accv[4 * u + 3] = fmaf(w, vv.w, accv[4 * u + 3]);
            }
        }

        const float sc = scg / sumw;
        const int   qq = q0 + 4 * tq2 + pass;
        float* orow = out + ((size_t)(b * TQ + qq)) * HD + g * 8;
        #pragma unroll
        for (int u = 0; u < 2; u++) {
            float4 ov = ((float4*)orow)[u];
            ov.x += sc * accv[4 * u + 0];
            ov.y += sc * accv[4 * u + 1];
            ov.z += sc * accv[4 * u + 2];
            ov.w += sc * accv[4 * u + 3];
            ((float4*)orow)[u] = ov;
        }
    }
}

// =========================================================================
extern "C" void kernel_launch(void* const* d_in, const int* in_sizes, int n_in,
                              void* d_out, int out_size) {
    const float* x        = (const float*)d_in[0];
    const float* ki       = (const float*)d_in[1];
    const float* vi       = (const float*)d_in[2];
    const float* mem_keys = (const float*)d_in[3];
    const float* mem_vals = (const float*)d_in[4];
    const float* Wq       = (const float*)d_in[5];
    const float* bq       = (const float*)d_in[6];
    const float* Wk       = (const float*)d_in[7];
    const float* bk       = (const float*)d_in[8];
    const float* Wv       = (const float*)d_in[9];
    const float* bv       = (const float*)d_in[10];
    const float* gate     = (const float*)d_in[11];
    const int*   idxp     = (const int*)d_in[12];
    float* out = (float*)d_out;

    cudaFuncSetAttribute(attn_kernel, cudaFuncAttributeMaxDynamicSharedMemorySize,
                         ATTN_SMEM);
    cudaFuncSetAttribute(mem_kernel, cudaFuncAttributeMaxDynamicSharedMemorySize,
                         MEM_SMEM);

    interleave_kernel<<<8192, 256>>>(mem_keys);
    copy_prefix_kernel<<<1024, 256>>>(ki, vi, idxp);
    proj_kernel<<<dim3(128, 3), 256>>>(x, Wq, Wk, Wv, bq, bk, bv);
    attn_kernel<<<dim3(32, 4, 2), 256, ATTN_SMEM>>>();
    attn_merge_kernel<<<1024, 256>>>(gate, out);
    mem_kernel<<<dim3(64, 4), 128, MEM_SMEM>>>(mem_vals, gate, out);
}